// round 3
// baseline (speedup 1.0000x reference)
#include <cuda_runtime.h>

#define NN 100000
#define NE 1600000
#define NG 512
#define NB 98   // ceil(NN/1024)

typedef unsigned long long u64;

// ---- scratch (device globals; no allocation allowed) ----
__device__ int   g_degout[NN];
__device__ int   g_degin[NN];
__device__ float g_rout[NN];
__device__ float g_rin[NN];
__device__ int   g_rowptr[NN + 1];
__device__ int   g_cur[NN];
__device__ int   g_partial[NB];
__device__ int   g_base[NB];
__device__ int   g_csrc[NE];
__device__ float g_agg1[NN * 128];   // 51.2 MB
__device__ float g_h1[NN * 256];     // 102.4 MB
__device__ float g_h2in[NN * 64];    // 25.6 MB
__device__ float g_gsum[NG * 64];
__device__ int   g_gcnt[NG];

// ---- packed fp32x2 helpers (sm_103a FFMA2 path) ---------------------------
__device__ __forceinline__ u64 pack2(float v) {
    u64 r;
    asm("mov.b64 %0, {%1, %1};" : "=l"(r) : "f"(v));
    return r;
}
#define FMA2(acc, a, b) asm("fma.rn.f32x2 %0, %1, %2, %0;" : "+l"(acc) : "l"(a), "l"(b))

// ---------------------------------------------------------------------------
__global__ void zero_small_kernel() {
    int i = blockIdx.x * blockDim.x + threadIdx.x;
    int stride = gridDim.x * blockDim.x;
    for (int j = i; j < NN; j += stride) { g_degout[j] = 0; g_degin[j] = 0; }
    for (int j = i; j < NG * 64; j += stride) g_gsum[j] = 0.f;
    for (int j = i; j < NG; j += stride) g_gcnt[j] = 0;
}

__global__ void degree_kernel(const int* __restrict__ src, const int* __restrict__ dst) {
    int e = blockIdx.x * blockDim.x + threadIdx.x;
    if (e < NE) {
        atomicAdd(&g_degout[src[e]], 1);
        atomicAdd(&g_degin[dst[e]], 1);
    }
}

__global__ void finalize_deg_kernel() {
    int i = blockIdx.x * blockDim.x + threadIdx.x;
    if (i < NN) {
        g_rout[i] = rsqrtf((float)max(g_degout[i], 1));
        g_rin[i]  = rsqrtf((float)max(g_degin[i], 1));
    }
}

// ---- 3-phase exclusive scan of g_degin -> g_rowptr -------------------------
__global__ void scanA_kernel() {
    __shared__ int sh[1024];
    int idx = blockIdx.x * 1024 + threadIdx.x;
    sh[threadIdx.x] = (idx < NN) ? g_degin[idx] : 0;
    __syncthreads();
    for (int off = 512; off > 0; off >>= 1) {
        if (threadIdx.x < off) sh[threadIdx.x] += sh[threadIdx.x + off];
        __syncthreads();
    }
    if (threadIdx.x == 0) g_partial[blockIdx.x] = sh[0];
}

__global__ void scanB_kernel() {
    __shared__ int sh[128];
    int t = threadIdx.x;
    sh[t] = (t < NB) ? g_partial[t] : 0;
    __syncthreads();
    if (t == 0) {
        int run = 0;
        for (int b = 0; b < NB; b++) { int v = sh[b]; sh[b] = run; run += v; }
        g_rowptr[NN] = run;
    }
    __syncthreads();
    if (t < NB) g_base[t] = sh[t];
}

__global__ void scanC_kernel() {
    __shared__ int sh[1024];
    int tid = threadIdx.x;
    int idx = blockIdx.x * 1024 + tid;
    int v = (idx < NN) ? g_degin[idx] : 0;
    sh[tid] = v;
    __syncthreads();
    for (int off = 1; off < 1024; off <<= 1) {
        int t2 = 0;
        if (tid >= off) t2 = sh[tid - off];
        __syncthreads();
        sh[tid] += t2;
        __syncthreads();
    }
    if (idx < NN) {
        int excl = sh[tid] - v + g_base[blockIdx.x];
        g_rowptr[idx] = excl;
        g_cur[idx] = excl;
    }
}

__global__ void scatter_kernel(const int* __restrict__ src, const int* __restrict__ dst) {
    int e = blockIdx.x * blockDim.x + threadIdx.x;
    if (e < NE) {
        int pos = atomicAdd(&g_cur[dst[e]], 1);
        g_csrc[pos] = src[e];
    }
}

// ---- layer-1 aggregation: warp per dst node, 4-way unrolled gather ---------
__global__ void agg1_kernel(const float* __restrict__ x) {
    int node = (blockIdx.x * blockDim.x + threadIdx.x) >> 5;
    if (node >= NN) return;
    int lane = threadIdx.x & 31;
    int beg = g_rowptr[node], end = g_rowptr[node + 1];
    float4 acc = make_float4(0.f, 0.f, 0.f, 0.f);
    int j = beg;
    for (; j + 3 < end; j += 4) {
        int s0 = g_csrc[j],     s1 = g_csrc[j + 1];
        int s2 = g_csrc[j + 2], s3 = g_csrc[j + 3];
        float r0 = g_rout[s0], r1 = g_rout[s1], r2 = g_rout[s2], r3 = g_rout[s3];
        float4 v0 = ((const float4*)(x + (size_t)s0 * 128))[lane];
        float4 v1 = ((const float4*)(x + (size_t)s1 * 128))[lane];
        float4 v2 = ((const float4*)(x + (size_t)s2 * 128))[lane];
        float4 v3 = ((const float4*)(x + (size_t)s3 * 128))[lane];
        acc.x += r0 * v0.x + r1 * v1.x + r2 * v2.x + r3 * v3.x;
        acc.y += r0 * v0.y + r1 * v1.y + r2 * v2.y + r3 * v3.y;
        acc.z += r0 * v0.z + r1 * v1.z + r2 * v2.z + r3 * v3.z;
        acc.w += r0 * v0.w + r1 * v1.w + r2 * v2.w + r3 * v3.w;
    }
    for (; j < end; j++) {
        int s = g_csrc[j];
        float r = g_rout[s];
        float4 v = ((const float4*)(x + (size_t)s * 128))[lane];
        acc.x += r * v.x; acc.y += r * v.y; acc.z += r * v.z; acc.w += r * v.w;
    }
    ((float4*)(g_agg1 + (size_t)node * 128))[lane] = acc;
}

// ---- FFMA2 GEMM: C = act( rowscale[i]*(A@B) + bias[j] ) --------------------
// BM=128, BK=16, 256 threads. BN/TM templated: (128,8) or (64,4). TN=8.
template<int BN, int TM>
__global__ void gemm_f32x2_kernel(const float* __restrict__ A, const float* __restrict__ B,
                                  float* __restrict__ C, int M, int N, int K,
                                  const float* __restrict__ rowscale,
                                  const float* __restrict__ bias, int relu) {
    constexpr int TN = 8;
    constexpr int TX = BN / TN;        // 16 or 8
    constexpr int NF4B = BN / 64;      // B float4s per thread per tile (2 or 1)
    __shared__ float As[16][136];
    __shared__ float Bs[16][BN + 8];

    int tid = threadIdx.x;
    int tx = tid % TX, ty = tid / TX;
    int rowBase = blockIdx.y * 128;
    int colBase = blockIdx.x * BN;

    u64 acc2[TM / 2][TN];
    #pragma unroll
    for (int p = 0; p < TM / 2; p++)
        #pragma unroll
        for (int n = 0; n < TN; n++) acc2[p][n] = 0ull;

    for (int k0 = 0; k0 < K; k0 += 16) {
        // A tile: 128 rows x 16 K. Each thread: 2 float4 along K at one row.
        {
            int arow = tid >> 1;
            int ak = (tid & 1) * 8;
            int gr = rowBase + arow;
            float4 av0 = make_float4(0.f, 0.f, 0.f, 0.f), av1 = av0;
            if (gr < M) {
                av0 = *(const float4*)(A + (size_t)gr * K + k0 + ak);
                av1 = *(const float4*)(A + (size_t)gr * K + k0 + ak + 4);
            }
            As[ak + 0][arow] = av0.x; As[ak + 1][arow] = av0.y;
            As[ak + 2][arow] = av0.z; As[ak + 3][arow] = av0.w;
            As[ak + 4][arow] = av1.x; As[ak + 5][arow] = av1.y;
            As[ak + 6][arow] = av1.z; As[ak + 7][arow] = av1.w;
        }
        // B tile: 16 K-rows x BN cols.
        #pragma unroll
        for (int jf = 0; jf < NF4B; jf++) {
            int idx = tid * NF4B + jf;            // float4 index
            int brow = idx / (BN / 4);
            int bcol = (idx % (BN / 4)) * 4;
            *(float4*)&Bs[brow][bcol] =
                *(const float4*)(B + (size_t)(k0 + brow) * N + colBase + bcol);
        }
        __syncthreads();

        #pragma unroll
        for (int k = 0; k < 16; k++) {
            // a: TM consecutive M-values -> TM/2 packed pairs (8B aligned)
            const u64* ap = (const u64*)&As[k][ty * TM];
            u64 a2[TM / 2];
            #pragma unroll
            for (int p = 0; p < TM / 2; p++) a2[p] = ap[p];
            float4 b03 = *(const float4*)&Bs[k][tx * TN];
            float4 b47 = *(const float4*)&Bs[k][tx * TN + 4];
            float b[TN] = {b03.x, b03.y, b03.z, b03.w, b47.x, b47.y, b47.z, b47.w};
            #pragma unroll
            for (int n = 0; n < TN; n++) {
                u64 bb = pack2(b[n]);
                #pragma unroll
                for (int p = 0; p < TM / 2; p++)
                    FMA2(acc2[p][n], a2[p], bb);
            }
        }
        __syncthreads();
    }

    // epilogue
    #pragma unroll
    for (int p = 0; p < TM / 2; p++) {
        #pragma unroll
        for (int h = 0; h < 2; h++) {
            int r = rowBase + ty * TM + 2 * p + h;
            if (r >= M) continue;
            float rs = rowscale[r];
            float v[TN];
            #pragma unroll
            for (int n = 0; n < TN; n++) {
                u64 a = acc2[p][n];
                unsigned bits = h ? (unsigned)(a >> 32) : (unsigned)(a & 0xffffffffu);
                float f = __uint_as_float(bits);
                int c = colBase + tx * TN + n;
                f = f * rs + (bias ? bias[c] : 0.f);
                if (relu) f = fmaxf(f, 0.f);
                v[n] = f;
            }
            float* cp = C + (size_t)r * N + colBase + tx * TN;
            *(float4*)cp       = make_float4(v[0], v[1], v[2], v[3]);
            *(float4*)(cp + 4) = make_float4(v[4], v[5], v[6], v[7]);
        }
    }
}

// ---- layer-2 aggregation fused with mean-pool reduction --------------------
__global__ void agg2_pool_kernel(const int* __restrict__ gid, const float* __restrict__ b2) {
    __shared__ float sv[8][64];
    __shared__ int sg[8];
    int wid = threadIdx.x >> 5, lane = threadIdx.x & 31;
    int node = blockIdx.x * 8 + wid;
    float2 acc = make_float2(0.f, 0.f);
    int gv = -1;
    if (node < NN) {
        int beg = g_rowptr[node], end = g_rowptr[node + 1];
        int j = beg;
        for (; j + 3 < end; j += 4) {
            int s0 = g_csrc[j],     s1 = g_csrc[j + 1];
            int s2 = g_csrc[j + 2], s3 = g_csrc[j + 3];
            float2 v0 = ((const float2*)(g_h2in + (size_t)s0 * 64))[lane];
            float2 v1 = ((const float2*)(g_h2in + (size_t)s1 * 64))[lane];
            float2 v2 = ((const float2*)(g_h2in + (size_t)s2 * 64))[lane];
            float2 v3 = ((const float2*)(g_h2in + (size_t)s3 * 64))[lane];
            acc.x += v0.x + v1.x + v2.x + v3.x;
            acc.y += v0.y + v1.y + v2.y + v3.y;
        }
        for (; j < end; j++) {
            int s = g_csrc[j];
            float2 v = ((const float2*)(g_h2in + (size_t)s * 64))[lane];
            acc.x += v.x; acc.y += v.y;
        }
        float ri = g_rin[node];
        float2 bb = ((const float2*)b2)[lane];
        acc.x = fmaxf(acc.x * ri + bb.x, 0.f);
        acc.y = fmaxf(acc.y * ri + bb.y, 0.f);
        gv = gid[node];
    }
    sv[wid][lane * 2]     = acc.x;
    sv[wid][lane * 2 + 1] = acc.y;
    if (lane == 0) sg[wid] = gv;
    __syncthreads();

    if (wid == 0) {
        int c0 = lane * 2;
        float a0 = 0.f, a1 = 0.f;
        int cnt = 0;
        int cur = sg[0];
        #pragma unroll
        for (int w = 0; w < 8; w++) {
            int gw = sg[w];
            if (gw != cur) {
                if (cur >= 0) {
                    atomicAdd(&g_gsum[cur * 64 + c0], a0);
                    atomicAdd(&g_gsum[cur * 64 + c0 + 1], a1);
                    if (lane == 0) atomicAdd(&g_gcnt[cur], cnt);
                }
                a0 = 0.f; a1 = 0.f; cnt = 0; cur = gw;
            }
            if (gw >= 0) { a0 += sv[w][c0]; a1 += sv[w][c0 + 1]; cnt++; }
        }
        if (cur >= 0) {
            atomicAdd(&g_gsum[cur * 64 + c0], a0);
            atomicAdd(&g_gsum[cur * 64 + c0 + 1], a1);
            if (lane == 0) atomicAdd(&g_gcnt[cur], cnt);
        }
    }
}

__global__ void classifier_kernel(const float* __restrict__ Wc1, const float* __restrict__ bc1,
                                  const float* __restrict__ Wc2, const float* __restrict__ bc2,
                                  const float* __restrict__ Wc3, const float* __restrict__ bc3,
                                  const float* __restrict__ Wc4, const float* __restrict__ bc4,
                                  float* __restrict__ out) {
    int g = blockIdx.x * blockDim.x + threadIdx.x;
    if (g >= NG) return;
    float inv = 1.f / fmaxf((float)g_gcnt[g], 1.f);
    float h[64];
    #pragma unroll
    for (int j = 0; j < 64; j++) h[j] = g_gsum[g * 64 + j] * inv;
    float t1[18];
    for (int j = 0; j < 18; j++) {
        float s = bc1[j];
        for (int k = 0; k < 64; k++) s += h[k] * Wc1[k * 18 + j];
        t1[j] = s;
    }
    float t2[12];
    for (int j = 0; j < 12; j++) {
        float s = bc2[j];
        for (int k = 0; k < 18; k++) s += t1[k] * Wc2[k * 12 + j];
        t2[j] = s;
    }
    float t3[6];
    for (int j = 0; j < 6; j++) {
        float s = bc3[j];
        for (int k = 0; k < 12; k++) s += t2[k] * Wc3[k * 6 + j];
        t3[j] = s;
    }
    for (int j = 0; j < 2; j++) {
        float s = bc4[j];
        for (int k = 0; k < 6; k++) s += t3[k] * Wc4[k * 2 + j];
        out[g * 2 + j] = s;
    }
}

// ---------------------------------------------------------------------------
extern "C" void kernel_launch(void* const* d_in, const int* in_sizes, int n_in,
                              void* d_out, int out_size) {
    const float* x   = (const float*)d_in[0];
    const int*   src = (const int*)d_in[1];
    const int*   dst = (const int*)d_in[2];
    const int*   gid = (const int*)d_in[3];
    const float* W1  = (const float*)d_in[4];
    const float* b1  = (const float*)d_in[5];
    const float* W2  = (const float*)d_in[6];
    const float* b2  = (const float*)d_in[7];
    const float* Wc1 = (const float*)d_in[8];
    const float* bc1 = (const float*)d_in[9];
    const float* Wc2 = (const float*)d_in[10];
    const float* bc2 = (const float*)d_in[11];
    const float* Wc3 = (const float*)d_in[12];
    const float* bc3 = (const float*)d_in[13];
    const float* Wc4 = (const float*)d_in[14];
    const float* bc4 = (const float*)d_in[15];
    float* out = (float*)d_out;

    float *p_agg1, *p_h1, *p_h2in, *p_rin, *p_rout;
    cudaGetSymbolAddress((void**)&p_agg1, g_agg1);
    cudaGetSymbolAddress((void**)&p_h1,   g_h1);
    cudaGetSymbolAddress((void**)&p_h2in, g_h2in);
    cudaGetSymbolAddress((void**)&p_rin,  g_rin);
    cudaGetSymbolAddress((void**)&p_rout, g_rout);

    zero_small_kernel<<<256, 256>>>();
    degree_kernel<<<(NE + 255) / 256, 256>>>(src, dst);
    finalize_deg_kernel<<<(NN + 255) / 256, 256>>>();

    // CSR build (dst-major)
    scanA_kernel<<<NB, 1024>>>();
    scanB_kernel<<<1, 128>>>();
    scanC_kernel<<<NB, 1024>>>();
    scatter_kernel<<<(NE + 255) / 256, 256>>>(src, dst);

    // layer 1: agg1 = segsum(x * rout); h1 = relu(rin * (agg1 @ W1) + b1)
    agg1_kernel<<<(NN * 32 + 255) / 256, 256>>>(x);
    dim3 grid1(256 / 128, (NN + 127) / 128);
    gemm_f32x2_kernel<128, 8><<<grid1, 256>>>(p_agg1, W1, p_h1, NN, 256, 128, p_rin, b1, 1);

    // layer 2: h2in = rout * (h1 @ W2); fused gather + pool
    dim3 grid2(1, (NN + 127) / 128);
    gemm_f32x2_kernel<64, 4><<<grid2, 256>>>(p_h1, W2, p_h2in, NN, 64, 256, p_rout, nullptr, 0);
    agg2_pool_kernel<<<(NN + 7) / 8, 256>>>(gid, b2);

    classifier_kernel<<<(NG + 255) / 256, 256>>>(Wc1, bc1, Wc2, bc2, Wc3, bc3, Wc4, bc4, out);
}

// round 4
// speedup vs baseline: 1.1748x; 1.1748x over previous
#include <cuda_runtime.h>

#define NN 100000
#define NE 1600000
#define NG 512
#define NB 98   // ceil(NN/1024)

// ---- scratch (device globals; no allocation allowed) ----
__device__ int   g_degout[NN];
__device__ int   g_degin[NN];
__device__ float g_rout[NN];
__device__ float g_rin[NN];
__device__ int   g_rowptr[NN + 1];
__device__ int   g_cur[NN];
__device__ int   g_partial[NB];
__device__ int   g_base[NB];
__device__ int   g_csrc[NE];
__device__ float g_agg1[NN * 128];   // 51.2 MB
__device__ float g_h1[NN * 256];     // 102.4 MB
__device__ float g_h2in[NN * 64];    // 25.6 MB
__device__ float g_gsum[NG * 64];
__device__ int   g_gcnt[NG];

// ---------------------------------------------------------------------------
__global__ void zero_small_kernel() {
    int i = blockIdx.x * blockDim.x + threadIdx.x;
    int stride = gridDim.x * blockDim.x;
    for (int j = i; j < NN; j += stride) { g_degout[j] = 0; g_degin[j] = 0; }
    for (int j = i; j < NG * 64; j += stride) g_gsum[j] = 0.f;
    for (int j = i; j < NG; j += stride) g_gcnt[j] = 0;
}

__global__ void degree_kernel(const int* __restrict__ src, const int* __restrict__ dst) {
    int e = blockIdx.x * blockDim.x + threadIdx.x;
    if (e < NE) {
        atomicAdd(&g_degout[src[e]], 1);
        atomicAdd(&g_degin[dst[e]], 1);
    }
}

__global__ void finalize_deg_kernel() {
    int i = blockIdx.x * blockDim.x + threadIdx.x;
    if (i < NN) {
        g_rout[i] = rsqrtf((float)max(g_degout[i], 1));
        g_rin[i]  = rsqrtf((float)max(g_degin[i], 1));
    }
}

// ---- 3-phase exclusive scan of g_degin -> g_rowptr -------------------------
__global__ void scanA_kernel() {
    __shared__ int sh[1024];
    int idx = blockIdx.x * 1024 + threadIdx.x;
    sh[threadIdx.x] = (idx < NN) ? g_degin[idx] : 0;
    __syncthreads();
    for (int off = 512; off > 0; off >>= 1) {
        if (threadIdx.x < off) sh[threadIdx.x] += sh[threadIdx.x + off];
        __syncthreads();
    }
    if (threadIdx.x == 0) g_partial[blockIdx.x] = sh[0];
}

__global__ void scanB_kernel() {
    __shared__ int sh[128];
    int t = threadIdx.x;
    sh[t] = (t < NB) ? g_partial[t] : 0;
    __syncthreads();
    if (t == 0) {
        int run = 0;
        for (int b = 0; b < NB; b++) { int v = sh[b]; sh[b] = run; run += v; }
        g_rowptr[NN] = run;
    }
    __syncthreads();
    if (t < NB) g_base[t] = sh[t];
}

__global__ void scanC_kernel() {
    __shared__ int sh[1024];
    int tid = threadIdx.x;
    int idx = blockIdx.x * 1024 + tid;
    int v = (idx < NN) ? g_degin[idx] : 0;
    sh[tid] = v;
    __syncthreads();
    for (int off = 1; off < 1024; off <<= 1) {
        int t2 = 0;
        if (tid >= off) t2 = sh[tid - off];
        __syncthreads();
        sh[tid] += t2;
        __syncthreads();
    }
    if (idx < NN) {
        int excl = sh[tid] - v + g_base[blockIdx.x];
        g_rowptr[idx] = excl;
        g_cur[idx] = excl;
    }
}

__global__ void scatter_kernel(const int* __restrict__ src, const int* __restrict__ dst) {
    int e = blockIdx.x * blockDim.x + threadIdx.x;
    if (e < NE) {
        int pos = atomicAdd(&g_cur[dst[e]], 1);
        g_csrc[pos] = src[e];
    }
}

// ---- layer-1 aggregation: warp per dst node, 4-way unrolled gather ---------
__global__ void agg1_kernel(const float* __restrict__ x) {
    int node = (blockIdx.x * blockDim.x + threadIdx.x) >> 5;
    if (node >= NN) return;
    int lane = threadIdx.x & 31;
    int beg = g_rowptr[node], end = g_rowptr[node + 1];
    float4 acc = make_float4(0.f, 0.f, 0.f, 0.f);
    int j = beg;
    for (; j + 3 < end; j += 4) {
        int s0 = g_csrc[j],     s1 = g_csrc[j + 1];
        int s2 = g_csrc[j + 2], s3 = g_csrc[j + 3];
        float r0 = g_rout[s0], r1 = g_rout[s1], r2 = g_rout[s2], r3 = g_rout[s3];
        float4 v0 = ((const float4*)(x + (size_t)s0 * 128))[lane];
        float4 v1 = ((const float4*)(x + (size_t)s1 * 128))[lane];
        float4 v2 = ((const float4*)(x + (size_t)s2 * 128))[lane];
        float4 v3 = ((const float4*)(x + (size_t)s3 * 128))[lane];
        acc.x += r0 * v0.x + r1 * v1.x + r2 * v2.x + r3 * v3.x;
        acc.y += r0 * v0.y + r1 * v1.y + r2 * v2.y + r3 * v3.y;
        acc.z += r0 * v0.z + r1 * v1.z + r2 * v2.z + r3 * v3.z;
        acc.w += r0 * v0.w + r1 * v1.w + r2 * v2.w + r3 * v3.w;
    }
    for (; j < end; j++) {
        int s = g_csrc[j];
        float r = g_rout[s];
        float4 v = ((const float4*)(x + (size_t)s * 128))[lane];
        acc.x += r * v.x; acc.y += r * v.y; acc.z += r * v.z; acc.w += r * v.w;
    }
    ((float4*)(g_agg1 + (size_t)node * 128))[lane] = acc;
}

// ---- scalar GEMM: C = act( rowscale[i]*(A@B) + bias[j] ) -------------------
// BM=128, BK=16, 256 threads. Template on BN/TN: (128,8) or (64,4). TM=8.
template<int BN, int TN>
__global__ void gemm_epilogue_kernel(const float* __restrict__ A, const float* __restrict__ B,
                                     float* __restrict__ C, int M, int N, int K,
                                     const float* __restrict__ rowscale,
                                     const float* __restrict__ bias, int relu) {
    constexpr int TM = 8;
    constexpr int TX = BN / TN;          // 16 in both configs
    constexpr int NF4B = (16 * BN / 4) / 256;  // B float4s per thread: 2 or 1
    __shared__ float As[16][132];
    __shared__ float Bs[16][BN + 4];

    int tid = threadIdx.x;
    int tx = tid % TX, ty = tid / TX;
    int rowBase = blockIdx.y * 128;
    int colBase = blockIdx.x * BN;
    float acc[TM][TN] = {};

    for (int k0 = 0; k0 < K; k0 += 16) {
        // A tile: 128 rows x 16 K. Each thread: 2 float4 along K at one row.
        {
            int arow = tid >> 1;
            int ak = (tid & 1) * 8;
            int gr = rowBase + arow;
            float4 av0 = make_float4(0.f, 0.f, 0.f, 0.f), av1 = av0;
            if (gr < M) {
                av0 = *(const float4*)(A + (size_t)gr * K + k0 + ak);
                av1 = *(const float4*)(A + (size_t)gr * K + k0 + ak + 4);
            }
            As[ak + 0][arow] = av0.x; As[ak + 1][arow] = av0.y;
            As[ak + 2][arow] = av0.z; As[ak + 3][arow] = av0.w;
            As[ak + 4][arow] = av1.x; As[ak + 5][arow] = av1.y;
            As[ak + 6][arow] = av1.z; As[ak + 7][arow] = av1.w;
        }
        // B tile: 16 K-rows x BN cols.
        #pragma unroll
        for (int jf = 0; jf < NF4B; jf++) {
            int idx = tid + jf * 256;            // float4 index
            int brow = idx / (BN / 4);
            int bcol = (idx % (BN / 4)) * 4;
            *(float4*)&Bs[brow][bcol] =
                *(const float4*)(B + (size_t)(k0 + brow) * N + colBase + bcol);
        }
        __syncthreads();

        #pragma unroll
        for (int k = 0; k < 16; k++) {
            float4 a03 = *(const float4*)&As[k][ty * TM];
            float4 a47 = *(const float4*)&As[k][ty * TM + 4];
            float a[TM] = {a03.x, a03.y, a03.z, a03.w, a47.x, a47.y, a47.z, a47.w};
            float b[TN];
            #pragma unroll
            for (int nf = 0; nf < TN / 4; nf++) {
                float4 b4 = *(const float4*)&Bs[k][tx * TN + nf * 4];
                b[nf * 4 + 0] = b4.x; b[nf * 4 + 1] = b4.y;
                b[nf * 4 + 2] = b4.z; b[nf * 4 + 3] = b4.w;
            }
            #pragma unroll
            for (int i = 0; i < TM; i++)
                #pragma unroll
                for (int n = 0; n < TN; n++)
                    acc[i][n] += a[i] * b[n];
        }
        __syncthreads();
    }

    // epilogue: vectorized stores
    #pragma unroll
    for (int i = 0; i < TM; i++) {
        int r = rowBase + ty * TM + i;
        if (r >= M) continue;
        float rs = rowscale[r];
        float v[TN];
        #pragma unroll
        for (int n = 0; n < TN; n++) {
            int c = colBase + tx * TN + n;
            float f = acc[i][n] * rs + (bias ? bias[c] : 0.f);
            if (relu) f = fmaxf(f, 0.f);
            v[n] = f;
        }
        float* cp = C + (size_t)r * N + colBase + tx * TN;
        #pragma unroll
        for (int nf = 0; nf < TN / 4; nf++)
            *(float4*)(cp + nf * 4) = make_float4(v[nf * 4], v[nf * 4 + 1],
                                                  v[nf * 4 + 2], v[nf * 4 + 3]);
    }
}

// ---- layer-2 aggregation fused with mean-pool reduction --------------------
__global__ void agg2_pool_kernel(const int* __restrict__ gid, const float* __restrict__ b2) {
    __shared__ float sv[8][64];
    __shared__ int sg[8];
    int wid = threadIdx.x >> 5, lane = threadIdx.x & 31;
    int node = blockIdx.x * 8 + wid;
    float2 acc = make_float2(0.f, 0.f);
    int gv = -1;
    if (node < NN) {
        int beg = g_rowptr[node], end = g_rowptr[node + 1];
        int j = beg;
        for (; j + 3 < end; j += 4) {
            int s0 = g_csrc[j],     s1 = g_csrc[j + 1];
            int s2 = g_csrc[j + 2], s3 = g_csrc[j + 3];
            float2 v0 = ((const float2*)(g_h2in + (size_t)s0 * 64))[lane];
            float2 v1 = ((const float2*)(g_h2in + (size_t)s1 * 64))[lane];
            float2 v2 = ((const float2*)(g_h2in + (size_t)s2 * 64))[lane];
            float2 v3 = ((const float2*)(g_h2in + (size_t)s3 * 64))[lane];
            acc.x += v0.x + v1.x + v2.x + v3.x;
            acc.y += v0.y + v1.y + v2.y + v3.y;
        }
        for (; j < end; j++) {
            int s = g_csrc[j];
            float2 v = ((const float2*)(g_h2in + (size_t)s * 64))[lane];
            acc.x += v.x; acc.y += v.y;
        }
        float ri = g_rin[node];
        float2 bb = ((const float2*)b2)[lane];
        acc.x = fmaxf(acc.x * ri + bb.x, 0.f);
        acc.y = fmaxf(acc.y * ri + bb.y, 0.f);
        gv = gid[node];
    }
    sv[wid][lane * 2]     = acc.x;
    sv[wid][lane * 2 + 1] = acc.y;
    if (lane == 0) sg[wid] = gv;
    __syncthreads();

    if (wid == 0) {
        int c0 = lane * 2;
        float a0 = 0.f, a1 = 0.f;
        int cnt = 0;
        int cur = sg[0];
        #pragma unroll
        for (int w = 0; w < 8; w++) {
            int gw = sg[w];
            if (gw != cur) {
                if (cur >= 0) {
                    atomicAdd(&g_gsum[cur * 64 + c0], a0);
                    atomicAdd(&g_gsum[cur * 64 + c0 + 1], a1);
                    if (lane == 0) atomicAdd(&g_gcnt[cur], cnt);
                }
                a0 = 0.f; a1 = 0.f; cnt = 0; cur = gw;
            }
            if (gw >= 0) { a0 += sv[w][c0]; a1 += sv[w][c0 + 1]; cnt++; }
        }
        if (cur >= 0) {
            atomicAdd(&g_gsum[cur * 64 + c0], a0);
            atomicAdd(&g_gsum[cur * 64 + c0 + 1], a1);
            if (lane == 0) atomicAdd(&g_gcnt[cur], cnt);
        }
    }
}

__global__ void classifier_kernel(const float* __restrict__ Wc1, const float* __restrict__ bc1,
                                  const float* __restrict__ Wc2, const float* __restrict__ bc2,
                                  const float* __restrict__ Wc3, const float* __restrict__ bc3,
                                  const float* __restrict__ Wc4, const float* __restrict__ bc4,
                                  float* __restrict__ out) {
    int g = blockIdx.x * blockDim.x + threadIdx.x;
    if (g >= NG) return;
    float inv = 1.f / fmaxf((float)g_gcnt[g], 1.f);
    float h[64];
    #pragma unroll
    for (int j = 0; j < 64; j++) h[j] = g_gsum[g * 64 + j] * inv;
    float t1[18];
    for (int j = 0; j < 18; j++) {
        float s = bc1[j];
        for (int k = 0; k < 64; k++) s += h[k] * Wc1[k * 18 + j];
        t1[j] = s;
    }
    float t2[12];
    for (int j = 0; j < 12; j++) {
        float s = bc2[j];
        for (int k = 0; k < 18; k++) s += t1[k] * Wc2[k * 12 + j];
        t2[j] = s;
    }
    float t3[6];
    for (int j = 0; j < 6; j++) {
        float s = bc3[j];
        for (int k = 0; k < 12; k++) s += t2[k] * Wc3[k * 6 + j];
        t3[j] = s;
    }
    for (int j = 0; j < 2; j++) {
        float s = bc4[j];
        for (int k = 0; k < 6; k++) s += t3[k] * Wc4[k * 2 + j];
        out[g * 2 + j] = s;
    }
}

// ---------------------------------------------------------------------------
extern "C" void kernel_launch(void* const* d_in, const int* in_sizes, int n_in,
                              void* d_out, int out_size) {
    const float* x   = (const float*)d_in[0];
    const int*   src = (const int*)d_in[1];
    const int*   dst = (const int*)d_in[2];
    const int*   gid = (const int*)d_in[3];
    const float* W1  = (const float*)d_in[4];
    const float* b1  = (const float*)d_in[5];
    const float* W2  = (const float*)d_in[6];
    const float* b2  = (const float*)d_in[7];
    const float* Wc1 = (const float*)d_in[8];
    const float* bc1 = (const float*)d_in[9];
    const float* Wc2 = (const float*)d_in[10];
    const float* bc2 = (const float*)d_in[11];
    const float* Wc3 = (const float*)d_in[12];
    const float* bc3 = (const float*)d_in[13];
    const float* Wc4 = (const float*)d_in[14];
    const float* bc4 = (const float*)d_in[15];
    float* out = (float*)d_out;

    float *p_agg1, *p_h1, *p_h2in, *p_rin, *p_rout;
    cudaGetSymbolAddress((void**)&p_agg1, g_agg1);
    cudaGetSymbolAddress((void**)&p_h1,   g_h1);
    cudaGetSymbolAddress((void**)&p_h2in, g_h2in);
    cudaGetSymbolAddress((void**)&p_rin,  g_rin);
    cudaGetSymbolAddress((void**)&p_rout, g_rout);

    zero_small_kernel<<<256, 256>>>();
    degree_kernel<<<(NE + 255) / 256, 256>>>(src, dst);
    finalize_deg_kernel<<<(NN + 255) / 256, 256>>>();

    // CSR build (dst-major)
    scanA_kernel<<<NB, 1024>>>();
    scanB_kernel<<<1, 128>>>();
    scanC_kernel<<<NB, 1024>>>();
    scatter_kernel<<<(NE + 255) / 256, 256>>>(src, dst);

    // layer 1: agg1 = segsum(x * rout); h1 = relu(rin * (agg1 @ W1) + b1)
    agg1_kernel<<<(NN * 32 + 255) / 256, 256>>>(x);
    dim3 grid1(256 / 128, (NN + 127) / 128);
    gemm_epilogue_kernel<128, 8><<<grid1, 256>>>(p_agg1, W1, p_h1, NN, 256, 128, p_rin, b1, 1);

    // layer 2: h2in = rout * (h1 @ W2); fused gather + pool
    dim3 grid2(1, (NN + 127) / 128);
    gemm_epilogue_kernel<64, 4><<<grid2, 256>>>(p_h1, W2, p_h2in, NN, 64, 256, p_rout, nullptr, 0);
    agg2_pool_kernel<<<(NN + 7) / 8, 256>>>(gid, b2);

    classifier_kernel<<<(NG + 255) / 256, 256>>>(Wc1, bc1, Wc2, bc2, Wc3, bc3, Wc4, bc4, out);
}

// round 5
// speedup vs baseline: 1.3755x; 1.1708x over previous
#include <cuda_runtime.h>

#define NN 100000
#define NE 1600000
#define NG 512
#define NB 98   // ceil(NN/1024)

// ---- scratch (device globals; no allocation allowed) ----
__device__ int   g_degout[NN];
__device__ int   g_degin[NN];
__device__ float g_rout[NN];
__device__ float g_rin[NN];
__device__ int   g_rowptr[NN + 1];
__device__ int   g_cur[NN];
__device__ int   g_partial[NB];
__device__ int   g_base[NB];
__device__ int   g_csrc[NE];
__device__ float g_agg1[NN * 128];   // 51.2 MB
__device__ float g_h1[NN * 256];     // 102.4 MB
__device__ float g_h2in[NN * 64];    // 25.6 MB
__device__ float g_gsum[NG * 64];
__device__ int   g_gcnt[NG];

// ---------------------------------------------------------------------------
__global__ void zero_small_kernel() {
    int i = blockIdx.x * blockDim.x + threadIdx.x;
    int stride = gridDim.x * blockDim.x;
    for (int j = i; j < NN; j += stride) { g_degout[j] = 0; g_degin[j] = 0; }
    for (int j = i; j < NG * 64; j += stride) g_gsum[j] = 0.f;
    for (int j = i; j < NG; j += stride) g_gcnt[j] = 0;
}

__global__ void degree_kernel(const int* __restrict__ src, const int* __restrict__ dst) {
    int e = blockIdx.x * blockDim.x + threadIdx.x;
    if (e < NE) {
        atomicAdd(&g_degout[src[e]], 1);
        atomicAdd(&g_degin[dst[e]], 1);
    }
}

__global__ void finalize_deg_kernel() {
    int i = blockIdx.x * blockDim.x + threadIdx.x;
    if (i < NN) {
        g_rout[i] = rsqrtf((float)max(g_degout[i], 1));
        g_rin[i]  = rsqrtf((float)max(g_degin[i], 1));
    }
}

// ---- 3-phase exclusive scan of g_degin -> g_rowptr -------------------------
__global__ void scanA_kernel() {
    __shared__ int sh[1024];
    int idx = blockIdx.x * 1024 + threadIdx.x;
    sh[threadIdx.x] = (idx < NN) ? g_degin[idx] : 0;
    __syncthreads();
    for (int off = 512; off > 0; off >>= 1) {
        if (threadIdx.x < off) sh[threadIdx.x] += sh[threadIdx.x + off];
        __syncthreads();
    }
    if (threadIdx.x == 0) g_partial[blockIdx.x] = sh[0];
}

__global__ void scanB_kernel() {
    __shared__ int sh[128];
    int t = threadIdx.x;
    sh[t] = (t < NB) ? g_partial[t] : 0;
    __syncthreads();
    if (t == 0) {
        int run = 0;
        for (int b = 0; b < NB; b++) { int v = sh[b]; sh[b] = run; run += v; }
        g_rowptr[NN] = run;
    }
    __syncthreads();
    if (t < NB) g_base[t] = sh[t];
}

__global__ void scanC_kernel() {
    __shared__ int sh[1024];
    int tid = threadIdx.x;
    int idx = blockIdx.x * 1024 + tid;
    int v = (idx < NN) ? g_degin[idx] : 0;
    sh[tid] = v;
    __syncthreads();
    for (int off = 1; off < 1024; off <<= 1) {
        int t2 = 0;
        if (tid >= off) t2 = sh[tid - off];
        __syncthreads();
        sh[tid] += t2;
        __syncthreads();
    }
    if (idx < NN) {
        int excl = sh[tid] - v + g_base[blockIdx.x];
        g_rowptr[idx] = excl;
        g_cur[idx] = excl;
    }
}

__global__ void scatter_kernel(const int* __restrict__ src, const int* __restrict__ dst) {
    int e = blockIdx.x * blockDim.x + threadIdx.x;
    if (e < NE) {
        int pos = atomicAdd(&g_cur[dst[e]], 1);
        g_csrc[pos] = src[e];
    }
}

// ---- layer-1 aggregation: warp per dst node, 4-way unrolled gather ---------
__global__ void agg1_kernel(const float* __restrict__ x) {
    int node = (blockIdx.x * blockDim.x + threadIdx.x) >> 5;
    if (node >= NN) return;
    int lane = threadIdx.x & 31;
    int beg = g_rowptr[node], end = g_rowptr[node + 1];
    float4 acc = make_float4(0.f, 0.f, 0.f, 0.f);
    int j = beg;
    for (; j + 3 < end; j += 4) {
        int s0 = g_csrc[j],     s1 = g_csrc[j + 1];
        int s2 = g_csrc[j + 2], s3 = g_csrc[j + 3];
        float r0 = g_rout[s0], r1 = g_rout[s1], r2 = g_rout[s2], r3 = g_rout[s3];
        float4 v0 = ((const float4*)(x + (size_t)s0 * 128))[lane];
        float4 v1 = ((const float4*)(x + (size_t)s1 * 128))[lane];
        float4 v2 = ((const float4*)(x + (size_t)s2 * 128))[lane];
        float4 v3 = ((const float4*)(x + (size_t)s3 * 128))[lane];
        acc.x += r0 * v0.x + r1 * v1.x + r2 * v2.x + r3 * v3.x;
        acc.y += r0 * v0.y + r1 * v1.y + r2 * v2.y + r3 * v3.y;
        acc.z += r0 * v0.z + r1 * v1.z + r2 * v2.z + r3 * v3.z;
        acc.w += r0 * v0.w + r1 * v1.w + r2 * v2.w + r3 * v3.w;
    }
    for (; j < end; j++) {
        int s = g_csrc[j];
        float r = g_rout[s];
        float4 v = ((const float4*)(x + (size_t)s * 128))[lane];
        acc.x += r * v.x; acc.y += r * v.y; acc.z += r * v.z; acc.w += r * v.w;
    }
    ((float4*)(g_agg1 + (size_t)node * 128))[lane] = acc;
}

// ---- TF32 tensor-core GEMM: C = act( rowscale[i]*(A@B) + bias[j] ) ---------
// mma.sync.m16n8k8 tf32. BM=128, BK=32, 256 threads (8 warps).
// k-permuted smem layout: element k goes to slot (k%4)*8 + k/4, so one
// LDS.128 per thread yields fragment data for two k-steps.
__device__ __forceinline__ float tf32r(float x) {
    float r;
    asm("cvt.rna.tf32.f32 %0, %1;" : "=f"(r) : "f"(x));
    return r;
}

#define MMA_TF32(c, a0, a1, a2, a3, b0, b1)                                   \
    asm volatile("mma.sync.aligned.m16n8k8.row.col.f32.tf32.tf32.f32 "        \
                 "{%0,%1,%2,%3}, {%4,%5,%6,%7}, {%8,%9}, {%0,%1,%2,%3};"      \
                 : "+f"(c[0]), "+f"(c[1]), "+f"(c[2]), "+f"(c[3])             \
                 : "r"(a0), "r"(a1), "r"(a2), "r"(a3), "r"(b0), "r"(b1))

template<int BN, int WARPS_M, int WARPS_N>
__global__ void gemm_tf32_kernel(const float* __restrict__ A, const float* __restrict__ B,
                                 float* __restrict__ C, int M, int N, int K,
                                 const float* __restrict__ rowscale,
                                 const float* __restrict__ bias, int relu) {
    constexpr int BM = 128, BK = 32;
    constexpr int WTM = BM / WARPS_M;      // warp tile M
    constexpr int WTN = BN / WARPS_N;      // warp tile N
    constexpr int MT = WTM / 16;           // mma tiles per warp, M
    constexpr int NT = WTN / 8;            // mma tiles per warp, N
    constexpr int AF4 = BM * BK / 4 / 256; // float4 loads per thread, A tile
    constexpr int BF4 = BK * BN / 4 / 256; // float4 loads per thread, B tile

    __shared__ float As[BM][36];   // [row][(k%4)*8 + k/4]
    __shared__ float Bs[BN][36];   // [col][(k%4)*8 + k/4]

    int tid = threadIdx.x;
    int warp = tid >> 5, lane = tid & 31;
    int g = lane >> 2, q = lane & 3;
    int wm = warp % WARPS_M, wn = warp / WARPS_M;
    int mBase = wm * WTM, nBase = wn * WTN;
    int rowBase = blockIdx.y * BM;
    int colBase = blockIdx.x * BN;

    float c[MT][NT][4];
    #pragma unroll
    for (int i = 0; i < MT; i++)
        #pragma unroll
        for (int j = 0; j < NT; j++)
            #pragma unroll
            for (int t = 0; t < 4; t++) c[i][j][t] = 0.f;

    for (int k0 = 0; k0 < K; k0 += BK) {
        // A tile -> permuted smem
        #pragma unroll
        for (int it = 0; it < AF4; it++) {
            int idx = tid + it * 256;
            int row = idx >> 3;
            int kc = (idx & 7) * 4;            // k&3 = 0..3, k>>2 = kc/4
            int gr = rowBase + row;
            float4 v = make_float4(0.f, 0.f, 0.f, 0.f);
            if (gr < M) v = *(const float4*)(A + (size_t)gr * K + k0 + kc);
            int s = kc >> 2;
            As[row][s]      = tf32r(v.x);
            As[row][8 + s]  = tf32r(v.y);
            As[row][16 + s] = tf32r(v.z);
            As[row][24 + s] = tf32r(v.w);
        }
        // B tile -> transposed permuted smem
        #pragma unroll
        for (int it = 0; it < BF4; it++) {
            int idx = tid + it * 256;
            int krow = idx / (BN / 4);
            int col = (idx % (BN / 4)) * 4;
            float4 v = *(const float4*)(B + (size_t)(k0 + krow) * N + colBase + col);
            int s = ((krow & 3) << 3) + (krow >> 2);
            Bs[col + 0][s] = tf32r(v.x);
            Bs[col + 1][s] = tf32r(v.y);
            Bs[col + 2][s] = tf32r(v.z);
            Bs[col + 3][s] = tf32r(v.w);
        }
        __syncthreads();

        #pragma unroll
        for (int ks2 = 0; ks2 < 2; ks2++) {     // pairs of k-steps
            uint4 alo[MT], ahi[MT], bf[NT];
            #pragma unroll
            for (int mt = 0; mt < MT; mt++) {
                alo[mt] = *(const uint4*)&As[mBase + mt * 16 + g][q * 8 + ks2 * 4];
                ahi[mt] = *(const uint4*)&As[mBase + mt * 16 + 8 + g][q * 8 + ks2 * 4];
            }
            #pragma unroll
            for (int nt = 0; nt < NT; nt++)
                bf[nt] = *(const uint4*)&Bs[nBase + nt * 8 + g][q * 8 + ks2 * 4];
            // sub = 0: components .x (which0) .y (which1); sub = 1: .z .w
            #pragma unroll
            for (int mt = 0; mt < MT; mt++)
                #pragma unroll
                for (int nt = 0; nt < NT; nt++)
                    MMA_TF32(c[mt][nt], alo[mt].x, ahi[mt].x, alo[mt].y, ahi[mt].y,
                             bf[nt].x, bf[nt].y);
            #pragma unroll
            for (int mt = 0; mt < MT; mt++)
                #pragma unroll
                for (int nt = 0; nt < NT; nt++)
                    MMA_TF32(c[mt][nt], alo[mt].z, ahi[mt].z, alo[mt].w, ahi[mt].w,
                             bf[nt].z, bf[nt].w);
        }
        __syncthreads();
    }

    // epilogue
    #pragma unroll
    for (int mt = 0; mt < MT; mt++) {
        int r0 = rowBase + mBase + mt * 16 + g;
        int r1 = r0 + 8;
        float rs0 = (r0 < M) ? rowscale[r0] : 0.f;
        float rs1 = (r1 < M) ? rowscale[r1] : 0.f;
        #pragma unroll
        for (int nt = 0; nt < NT; nt++) {
            int cc = colBase + nBase + nt * 8 + 2 * q;
            float bb0 = bias ? bias[cc] : 0.f;
            float bb1 = bias ? bias[cc + 1] : 0.f;
            if (r0 < M) {
                float v0 = c[mt][nt][0] * rs0 + bb0;
                float v1 = c[mt][nt][1] * rs0 + bb1;
                if (relu) { v0 = fmaxf(v0, 0.f); v1 = fmaxf(v1, 0.f); }
                *(float2*)(C + (size_t)r0 * N + cc) = make_float2(v0, v1);
            }
            if (r1 < M) {
                float v0 = c[mt][nt][2] * rs1 + bb0;
                float v1 = c[mt][nt][3] * rs1 + bb1;
                if (relu) { v0 = fmaxf(v0, 0.f); v1 = fmaxf(v1, 0.f); }
                *(float2*)(C + (size_t)r1 * N + cc) = make_float2(v0, v1);
            }
        }
    }
}

// ---- layer-2 aggregation fused with mean-pool reduction --------------------
__global__ void agg2_pool_kernel(const int* __restrict__ gid, const float* __restrict__ b2) {
    __shared__ float sv[8][64];
    __shared__ int sg[8];
    int wid = threadIdx.x >> 5, lane = threadIdx.x & 31;
    int node = blockIdx.x * 8 + wid;
    float2 acc = make_float2(0.f, 0.f);
    int gv = -1;
    if (node < NN) {
        int beg = g_rowptr[node], end = g_rowptr[node + 1];
        int j = beg;
        for (; j + 3 < end; j += 4) {
            int s0 = g_csrc[j],     s1 = g_csrc[j + 1];
            int s2 = g_csrc[j + 2], s3 = g_csrc[j + 3];
            float2 v0 = ((const float2*)(g_h2in + (size_t)s0 * 64))[lane];
            float2 v1 = ((const float2*)(g_h2in + (size_t)s1 * 64))[lane];
            float2 v2 = ((const float2*)(g_h2in + (size_t)s2 * 64))[lane];
            float2 v3 = ((const float2*)(g_h2in + (size_t)s3 * 64))[lane];
            acc.x += v0.x + v1.x + v2.x + v3.x;
            acc.y += v0.y + v1.y + v2.y + v3.y;
        }
        for (; j < end; j++) {
            int s = g_csrc[j];
            float2 v = ((const float2*)(g_h2in + (size_t)s * 64))[lane];
            acc.x += v.x; acc.y += v.y;
        }
        float ri = g_rin[node];
        float2 bb = ((const float2*)b2)[lane];
        acc.x = fmaxf(acc.x * ri + bb.x, 0.f);
        acc.y = fmaxf(acc.y * ri + bb.y, 0.f);
        gv = gid[node];
    }
    sv[wid][lane * 2]     = acc.x;
    sv[wid][lane * 2 + 1] = acc.y;
    if (lane == 0) sg[wid] = gv;
    __syncthreads();

    if (wid == 0) {
        int c0 = lane * 2;
        float a0 = 0.f, a1 = 0.f;
        int cnt = 0;
        int cur = sg[0];
        #pragma unroll
        for (int w = 0; w < 8; w++) {
            int gw = sg[w];
            if (gw != cur) {
                if (cur >= 0) {
                    atomicAdd(&g_gsum[cur * 64 + c0], a0);
                    atomicAdd(&g_gsum[cur * 64 + c0 + 1], a1);
                    if (lane == 0) atomicAdd(&g_gcnt[cur], cnt);
                }
                a0 = 0.f; a1 = 0.f; cnt = 0; cur = gw;
            }
            if (gw >= 0) { a0 += sv[w][c0]; a1 += sv[w][c0 + 1]; cnt++; }
        }
        if (cur >= 0) {
            atomicAdd(&g_gsum[cur * 64 + c0], a0);
            atomicAdd(&g_gsum[cur * 64 + c0 + 1], a1);
            if (lane == 0) atomicAdd(&g_gcnt[cur], cnt);
        }
    }
}

__global__ void classifier_kernel(const float* __restrict__ Wc1, const float* __restrict__ bc1,
                                  const float* __restrict__ Wc2, const float* __restrict__ bc2,
                                  const float* __restrict__ Wc3, const float* __restrict__ bc3,
                                  const float* __restrict__ Wc4, const float* __restrict__ bc4,
                                  float* __restrict__ out) {
    int g = blockIdx.x * blockDim.x + threadIdx.x;
    if (g >= NG) return;
    float inv = 1.f / fmaxf((float)g_gcnt[g], 1.f);
    float h[64];
    #pragma unroll
    for (int j = 0; j < 64; j++) h[j] = g_gsum[g * 64 + j] * inv;
    float t1[18];
    for (int j = 0; j < 18; j++) {
        float s = bc1[j];
        for (int k = 0; k < 64; k++) s += h[k] * Wc1[k * 18 + j];
        t1[j] = s;
    }
    float t2[12];
    for (int j = 0; j < 12; j++) {
        float s = bc2[j];
        for (int k = 0; k < 18; k++) s += t1[k] * Wc2[k * 12 + j];
        t2[j] = s;
    }
    float t3[6];
    for (int j = 0; j < 6; j++) {
        float s = bc3[j];
        for (int k = 0; k < 12; k++) s += t2[k] * Wc3[k * 6 + j];
        t3[j] = s;
    }
    for (int j = 0; j < 2; j++) {
        float s = bc4[j];
        for (int k = 0; k < 6; k++) s += t3[k] * Wc4[k * 2 + j];
        out[g * 2 + j] = s;
    }
}

// ---------------------------------------------------------------------------
extern "C" void kernel_launch(void* const* d_in, const int* in_sizes, int n_in,
                              void* d_out, int out_size) {
    const float* x   = (const float*)d_in[0];
    const int*   src = (const int*)d_in[1];
    const int*   dst = (const int*)d_in[2];
    const int*   gid = (const int*)d_in[3];
    const float* W1  = (const float*)d_in[4];
    const float* b1  = (const float*)d_in[5];
    const float* W2  = (const float*)d_in[6];
    const float* b2  = (const float*)d_in[7];
    const float* Wc1 = (const float*)d_in[8];
    const float* bc1 = (const float*)d_in[9];
    const float* Wc2 = (const float*)d_in[10];
    const float* bc2 = (const float*)d_in[11];
    const float* Wc3 = (const float*)d_in[12];
    const float* bc3 = (const float*)d_in[13];
    const float* Wc4 = (const float*)d_in[14];
    const float* bc4 = (const float*)d_in[15];
    float* out = (float*)d_out;

    float *p_agg1, *p_h1, *p_h2in, *p_rin, *p_rout;
    cudaGetSymbolAddress((void**)&p_agg1, g_agg1);
    cudaGetSymbolAddress((void**)&p_h1,   g_h1);
    cudaGetSymbolAddress((void**)&p_h2in, g_h2in);
    cudaGetSymbolAddress((void**)&p_rin,  g_rin);
    cudaGetSymbolAddress((void**)&p_rout, g_rout);

    zero_small_kernel<<<256, 256>>>();
    degree_kernel<<<(NE + 255) / 256, 256>>>(src, dst);
    finalize_deg_kernel<<<(NN + 255) / 256, 256>>>();

    // CSR build (dst-major)
    scanA_kernel<<<NB, 1024>>>();
    scanB_kernel<<<1, 128>>>();
    scanC_kernel<<<NB, 1024>>>();
    scatter_kernel<<<(NE + 255) / 256, 256>>>(src, dst);

    // layer 1: agg1 = segsum(x * rout); h1 = relu(rin * (agg1 @ W1) + b1)
    agg1_kernel<<<(NN * 32 + 255) / 256, 256>>>(x);
    dim3 grid1(256 / 128, (NN + 127) / 128);
    gemm_tf32_kernel<128, 2, 4><<<grid1, 256>>>(p_agg1, W1, p_h1, NN, 256, 128, p_rin, b1, 1);

    // layer 2: h2in = rout * (h1 @ W2); fused gather + pool
    dim3 grid2(1, (NN + 127) / 128);
    gemm_tf32_kernel<64, 4, 2><<<grid2, 256>>>(p_h1, W2, p_h2in, NN, 64, 256, p_rout, nullptr, 0);
    agg2_pool_kernel<<<(NN + 7) / 8, 256>>>(gid, b2);

    classifier_kernel<<<(NG + 255) / 256, 256>>>(Wc1, bc1, Wc2, bc2, Wc3, bc3, Wc4, bc4, out);
}

// round 6
// speedup vs baseline: 1.5189x; 1.1042x over previous
#include <cuda_runtime.h>

#define NN 100000
#define NE 1600000
#define NG 512
#define NB 98   // ceil(NN/1024)

// ---- scratch (device globals; no allocation allowed) ----
__device__ int   g_degout[NN];
__device__ int   g_degin[NN];
__device__ float g_rout[NN];
__device__ float g_rin[NN];
__device__ int   g_rowptr[NN + 1];
__device__ int   g_cur[NN];
__device__ int   g_partial[NB];
__device__ int   g_base[NB];
__device__ int   g_csrc[NE];
__device__ float g_agg1[NN * 128];   // 51.2 MB
__device__ float g_h2in[NN * 64];    // 25.6 MB
__device__ float g_gsum[NG * 64];
__device__ int   g_gcnt[NG];

// ---------------------------------------------------------------------------
__global__ void zero_small_kernel() {
    int i = blockIdx.x * blockDim.x + threadIdx.x;
    int stride = gridDim.x * blockDim.x;
    for (int j = i; j < NN; j += stride) { g_degout[j] = 0; g_degin[j] = 0; }
    for (int j = i; j < NG * 64; j += stride) g_gsum[j] = 0.f;
    for (int j = i; j < NG; j += stride) g_gcnt[j] = 0;
}

__global__ void degree_kernel(const int* __restrict__ src, const int* __restrict__ dst) {
    int e = blockIdx.x * blockDim.x + threadIdx.x;
    if (e < NE) {
        atomicAdd(&g_degout[src[e]], 1);
        atomicAdd(&g_degin[dst[e]], 1);
    }
}

__global__ void finalize_deg_kernel() {
    int i = blockIdx.x * blockDim.x + threadIdx.x;
    if (i < NN) {
        g_rout[i] = rsqrtf((float)max(g_degout[i], 1));
        g_rin[i]  = rsqrtf((float)max(g_degin[i], 1));
    }
}

// ---- 3-phase exclusive scan of g_degin -> g_rowptr -------------------------
__global__ void scanA_kernel() {
    __shared__ int sh[1024];
    int idx = blockIdx.x * 1024 + threadIdx.x;
    sh[threadIdx.x] = (idx < NN) ? g_degin[idx] : 0;
    __syncthreads();
    for (int off = 512; off > 0; off >>= 1) {
        if (threadIdx.x < off) sh[threadIdx.x] += sh[threadIdx.x + off];
        __syncthreads();
    }
    if (threadIdx.x == 0) g_partial[blockIdx.x] = sh[0];
}

__global__ void scanB_kernel() {
    __shared__ int sh[128];
    int t = threadIdx.x;
    sh[t] = (t < NB) ? g_partial[t] : 0;
    __syncthreads();
    if (t == 0) {
        int run = 0;
        for (int b = 0; b < NB; b++) { int v = sh[b]; sh[b] = run; run += v; }
        g_rowptr[NN] = run;
    }
    __syncthreads();
    if (t < NB) g_base[t] = sh[t];
}

__global__ void scanC_kernel() {
    __shared__ int sh[1024];
    int tid = threadIdx.x;
    int idx = blockIdx.x * 1024 + tid;
    int v = (idx < NN) ? g_degin[idx] : 0;
    sh[tid] = v;
    __syncthreads();
    for (int off = 1; off < 1024; off <<= 1) {
        int t2 = 0;
        if (tid >= off) t2 = sh[tid - off];
        __syncthreads();
        sh[tid] += t2;
        __syncthreads();
    }
    if (idx < NN) {
        int excl = sh[tid] - v + g_base[blockIdx.x];
        g_rowptr[idx] = excl;
        g_cur[idx] = excl;
    }
}

__global__ void scatter_kernel(const int* __restrict__ src, const int* __restrict__ dst) {
    int e = blockIdx.x * blockDim.x + threadIdx.x;
    if (e < NE) {
        int pos = atomicAdd(&g_cur[dst[e]], 1);
        g_csrc[pos] = src[e];
    }
}

// ---- layer-1 aggregation: warp per dst node, 4-way unrolled gather ---------
__global__ void agg1_kernel(const float* __restrict__ x) {
    int node = (blockIdx.x * blockDim.x + threadIdx.x) >> 5;
    if (node >= NN) return;
    int lane = threadIdx.x & 31;
    int beg = g_rowptr[node], end = g_rowptr[node + 1];
    float4 acc = make_float4(0.f, 0.f, 0.f, 0.f);
    int j = beg;
    for (; j + 3 < end; j += 4) {
        int s0 = g_csrc[j],     s1 = g_csrc[j + 1];
        int s2 = g_csrc[j + 2], s3 = g_csrc[j + 3];
        float r0 = g_rout[s0], r1 = g_rout[s1], r2 = g_rout[s2], r3 = g_rout[s3];
        float4 v0 = ((const float4*)(x + (size_t)s0 * 128))[lane];
        float4 v1 = ((const float4*)(x + (size_t)s1 * 128))[lane];
        float4 v2 = ((const float4*)(x + (size_t)s2 * 128))[lane];
        float4 v3 = ((const float4*)(x + (size_t)s3 * 128))[lane];
        acc.x += r0 * v0.x + r1 * v1.x + r2 * v2.x + r3 * v3.x;
        acc.y += r0 * v0.y + r1 * v1.y + r2 * v2.y + r3 * v3.y;
        acc.z += r0 * v0.z + r1 * v1.z + r2 * v2.z + r3 * v3.z;
        acc.w += r0 * v0.w + r1 * v1.w + r2 * v2.w + r3 * v3.w;
    }
    for (; j < end; j++) {
        int s = g_csrc[j];
        float r = g_rout[s];
        float4 v = ((const float4*)(x + (size_t)s * 128))[lane];
        acc.x += r * v.x; acc.y += r * v.y; acc.z += r * v.z; acc.w += r * v.w;
    }
    ((float4*)(g_agg1 + (size_t)node * 128))[lane] = acc;
}

// ---- fused TF32 double-GEMM --------------------------------------------------
// h2in = rout ⊙ ( relu( rin ⊙ (agg1 @ W1) + b1 ) @ W2 )
// BM=64 rows per block, 256 threads (8 warps, WM=2 x WN=4).
// h1 never touches global memory: each 64-col quarter of h1 is produced by
// MMA1, epilogued, and staged (tf32) in the MMA2 A-operand permuted layout.
__device__ __forceinline__ float tf32r(float x) {
    float r;
    asm("cvt.rna.tf32.f32 %0, %1;" : "=f"(r) : "f"(x));
    return r;
}

#define MMA_TF32(c, a0, a1, a2, a3, b0, b1)                                   \
    asm volatile("mma.sync.aligned.m16n8k8.row.col.f32.tf32.tf32.f32 "        \
                 "{%0,%1,%2,%3}, {%4,%5,%6,%7}, {%8,%9}, {%0,%1,%2,%3};"      \
                 : "+f"(c[0]), "+f"(c[1]), "+f"(c[2]), "+f"(c[3])             \
                 : "r"(a0), "r"(a1), "r"(a2), "r"(a3), "r"(b0), "r"(b1))

#define FUSED_SMEM_FLOATS (4*64*36 + 4*64*36 + 2*64*36 + 2*64*36)

__global__ void gemm_fused_kernel(const float* __restrict__ A,   // agg1 [M,128]
                                  const float* __restrict__ W1,  // [128,256]
                                  const float* __restrict__ W2,  // [256,64]
                                  const float* __restrict__ rin,
                                  const float* __restrict__ b1,
                                  const float* __restrict__ rout,
                                  float* __restrict__ Cout,      // h2in [M,64]
                                  int M) {
    extern __shared__ float sm[];
    float* As  = sm;                     // [4 kchunk][64 row][36]
    float* Bs1 = As + 4 * 64 * 36;       // [4 kchunk][64 col][36]
    float* Bs2 = Bs1 + 4 * 64 * 36;      // [2 kchunk][64 col][36]
    float* Hs  = Bs2 + 2 * 64 * 36;      // [2 kchunk][64 row][36]

    int tid = threadIdx.x;
    int warp = tid >> 5, lane = tid & 31;
    int g = lane >> 2, q = lane & 3;
    int wm = warp & 1, wn = warp >> 1;
    int rowBase = blockIdx.x * 64;

    // per-thread row scales (rows wm*32 + mt*16 + g and +8)
    float rs0[2], rs1[2], ro0[2], ro1[2];
    #pragma unroll
    for (int mt = 0; mt < 2; mt++) {
        int r = rowBase + wm * 32 + mt * 16 + g;
        rs0[mt] = (r < M) ? rin[r] : 0.f;
        ro0[mt] = (r < M) ? rout[r] : 0.f;
        rs1[mt] = (r + 8 < M) ? rin[r + 8] : 0.f;
        ro1[mt] = (r + 8 < M) ? rout[r + 8] : 0.f;
    }

    // prologue: A block [64 x 128] -> As (tf32, permuted), kept all kernel
    #pragma unroll
    for (int kc = 0; kc < 4; kc++) {
        #pragma unroll
        for (int it = 0; it < 2; it++) {
            int idx = tid + it * 256;            // 0..511
            int row = idx >> 3;
            int k4 = (idx & 7) * 4;
            int gr = rowBase + row;
            float4 v = make_float4(0.f, 0.f, 0.f, 0.f);
            if (gr < M) v = *(const float4*)(A + (size_t)gr * 128 + kc * 32 + k4);
            int s = k4 >> 2;
            float* p = As + (kc * 64 + row) * 36;
            p[s]      = tf32r(v.x);
            p[8 + s]  = tf32r(v.y);
            p[16 + s] = tf32r(v.z);
            p[24 + s] = tf32r(v.w);
        }
    }

    float c2[2][2][4] = {};

    for (int qtr = 0; qtr < 4; qtr++) {
        // ---- load W1 tile: k=0..127, cols qtr*64..+64 -> Bs1 ----
        #pragma unroll
        for (int kc = 0; kc < 4; kc++) {
            #pragma unroll
            for (int it = 0; it < 2; it++) {
                int idx = tid + it * 256;
                int krow = idx >> 4;             // 0..31
                int col = (idx & 15) * 4;
                float4 v = *(const float4*)(W1 + (size_t)(kc * 32 + krow) * 256 + qtr * 64 + col);
                int s = ((krow & 3) << 3) + (krow >> 2);
                Bs1[(kc * 64 + col + 0) * 36 + s] = tf32r(v.x);
                Bs1[(kc * 64 + col + 1) * 36 + s] = tf32r(v.y);
                Bs1[(kc * 64 + col + 2) * 36 + s] = tf32r(v.z);
                Bs1[(kc * 64 + col + 3) * 36 + s] = tf32r(v.w);
            }
        }
        __syncthreads();   // Bs1 ready; also fences prev quarter's MMA2 reads

        // ---- MMA1: c1 = A_tile @ W1_quarter  (64x64, K=128) ----
        float c1[2][2][4] = {};
        #pragma unroll
        for (int kc = 0; kc < 4; kc++) {
            #pragma unroll
            for (int ks2 = 0; ks2 < 2; ks2++) {
                uint4 alo[2], ahi[2], bf[2];
                #pragma unroll
                for (int mt = 0; mt < 2; mt++) {
                    const float* p = As + (kc * 64 + wm * 32 + mt * 16 + g) * 36 + q * 8 + ks2 * 4;
                    alo[mt] = *(const uint4*)p;
                    ahi[mt] = *(const uint4*)(p + 8 * 36);
                }
                #pragma unroll
                for (int nt = 0; nt < 2; nt++)
                    bf[nt] = *(const uint4*)(Bs1 + (kc * 64 + wn * 16 + nt * 8 + g) * 36 + q * 8 + ks2 * 4);
                #pragma unroll
                for (int mt = 0; mt < 2; mt++)
                    #pragma unroll
                    for (int nt = 0; nt < 2; nt++) {
                        MMA_TF32(c1[mt][nt], alo[mt].x, ahi[mt].x, alo[mt].y, ahi[mt].y,
                                 bf[nt].x, bf[nt].y);
                        MMA_TF32(c1[mt][nt], alo[mt].z, ahi[mt].z, alo[mt].w, ahi[mt].w,
                                 bf[nt].z, bf[nt].w);
                    }
            }
        }

        // ---- epilogue1: rin*c1 + b1, relu, -> Hs (tf32, MMA2-A layout) ----
        #pragma unroll
        for (int nt = 0; nt < 2; nt++) {
            int cL0 = wn * 16 + nt * 8 + 2 * q;          // 0..63 within quarter
            float2 bb = *(const float2*)(b1 + qtr * 64 + cL0);
            int chunk = cL0 >> 5;
            int c32 = cL0 & 31;
            int slot0 = (c32 & 3) * 8 + (c32 >> 2);      // slot of col cL0; cL0+1 -> +8
            #pragma unroll
            for (int mt = 0; mt < 2; mt++) {
                int r0 = wm * 32 + mt * 16 + g;
                float v00 = fmaxf(c1[mt][nt][0] * rs0[mt] + bb.x, 0.f);
                float v01 = fmaxf(c1[mt][nt][1] * rs0[mt] + bb.y, 0.f);
                float v10 = fmaxf(c1[mt][nt][2] * rs1[mt] + bb.x, 0.f);
                float v11 = fmaxf(c1[mt][nt][3] * rs1[mt] + bb.y, 0.f);
                float* hp0 = Hs + (chunk * 64 + r0) * 36;
                float* hp1 = hp0 + 8 * 36;
                hp0[slot0]     = tf32r(v00);
                hp0[slot0 + 8] = tf32r(v01);
                hp1[slot0]     = tf32r(v10);
                hp1[slot0 + 8] = tf32r(v11);
            }
        }

        // ---- load W2 tile: rows qtr*64..+64, cols 0..63 -> Bs2 ----
        #pragma unroll
        for (int cc = 0; cc < 2; cc++) {
            #pragma unroll
            for (int it = 0; it < 2; it++) {
                int idx = tid + it * 256;
                int krow = idx >> 4;
                int col = (idx & 15) * 4;
                float4 v = *(const float4*)(W2 + (size_t)(qtr * 64 + cc * 32 + krow) * 64 + col);
                int s = ((krow & 3) << 3) + (krow >> 2);
                Bs2[(cc * 64 + col + 0) * 36 + s] = tf32r(v.x);
                Bs2[(cc * 64 + col + 1) * 36 + s] = tf32r(v.y);
                Bs2[(cc * 64 + col + 2) * 36 + s] = tf32r(v.z);
                Bs2[(cc * 64 + col + 3) * 36 + s] = tf32r(v.w);
            }
        }
        __syncthreads();   // Hs + Bs2 ready

        // ---- MMA2: c2 += h1_quarter @ W2_quarter  (64x64, K=64) ----
        #pragma unroll
        for (int cc = 0; cc < 2; cc++) {
            #pragma unroll
            for (int ks2 = 0; ks2 < 2; ks2++) {
                uint4 alo[2], ahi[2], bf[2];
                #pragma unroll
                for (int mt = 0; mt < 2; mt++) {
                    const float* p = Hs + (cc * 64 + wm * 32 + mt * 16 + g) * 36 + q * 8 + ks2 * 4;
                    alo[mt] = *(const uint4*)p;
                    ahi[mt] = *(const uint4*)(p + 8 * 36);
                }
                #pragma unroll
                for (int nt = 0; nt < 2; nt++)
                    bf[nt] = *(const uint4*)(Bs2 + (cc * 64 + wn * 16 + nt * 8 + g) * 36 + q * 8 + ks2 * 4);
                #pragma unroll
                for (int mt = 0; mt < 2; mt++)
                    #pragma unroll
                    for (int nt = 0; nt < 2; nt++) {
                        MMA_TF32(c2[mt][nt], alo[mt].x, ahi[mt].x, alo[mt].y, ahi[mt].y,
                                 bf[nt].x, bf[nt].y);
                        MMA_TF32(c2[mt][nt], alo[mt].z, ahi[mt].z, alo[mt].w, ahi[mt].w,
                                 bf[nt].z, bf[nt].w);
                    }
            }
        }
        __syncthreads();   // MMA2 done before next quarter overwrites Bs1/Hs/Bs2
    }

    // ---- final epilogue: h2in = rout * c2 ----
    #pragma unroll
    for (int mt = 0; mt < 2; mt++) {
        int r0 = rowBase + wm * 32 + mt * 16 + g;
        #pragma unroll
        for (int nt = 0; nt < 2; nt++) {
            int c0 = wn * 16 + nt * 8 + 2 * q;
            if (r0 < M)
                *(float2*)(Cout + (size_t)r0 * 64 + c0) =
                    make_float2(c2[mt][nt][0] * ro0[mt], c2[mt][nt][1] * ro0[mt]);
            if (r0 + 8 < M)
                *(float2*)(Cout + (size_t)(r0 + 8) * 64 + c0) =
                    make_float2(c2[mt][nt][2] * ro1[mt], c2[mt][nt][3] * ro1[mt]);
        }
    }
}

// ---- layer-2 aggregation fused with mean-pool reduction --------------------
__global__ void agg2_pool_kernel(const int* __restrict__ gid, const float* __restrict__ b2) {
    __shared__ float sv[8][64];
    __shared__ int sg[8];
    int wid = threadIdx.x >> 5, lane = threadIdx.x & 31;
    int node = blockIdx.x * 8 + wid;
    float2 acc = make_float2(0.f, 0.f);
    int gv = -1;
    if (node < NN) {
        int beg = g_rowptr[node], end = g_rowptr[node + 1];
        int j = beg;
        for (; j + 3 < end; j += 4) {
            int s0 = g_csrc[j],     s1 = g_csrc[j + 1];
            int s2 = g_csrc[j + 2], s3 = g_csrc[j + 3];
            float2 v0 = ((const float2*)(g_h2in + (size_t)s0 * 64))[lane];
            float2 v1 = ((const float2*)(g_h2in + (size_t)s1 * 64))[lane];
            float2 v2 = ((const float2*)(g_h2in + (size_t)s2 * 64))[lane];
            float2 v3 = ((const float2*)(g_h2in + (size_t)s3 * 64))[lane];
            acc.x += v0.x + v1.x + v2.x + v3.x;
            acc.y += v0.y + v1.y + v2.y + v3.y;
        }
        for (; j < end; j++) {
            int s = g_csrc[j];
            float2 v = ((const float2*)(g_h2in + (size_t)s * 64))[lane];
            acc.x += v.x; acc.y += v.y;
        }
        float ri = g_rin[node];
        float2 bb = ((const float2*)b2)[lane];
        acc.x = fmaxf(acc.x * ri + bb.x, 0.f);
        acc.y = fmaxf(acc.y * ri + bb.y, 0.f);
        gv = gid[node];
    }
    sv[wid][lane * 2]     = acc.x;
    sv[wid][lane * 2 + 1] = acc.y;
    if (lane == 0) sg[wid] = gv;
    __syncthreads();

    if (wid == 0) {
        int c0 = lane * 2;
        float a0 = 0.f, a1 = 0.f;
        int cnt = 0;
        int cur = sg[0];
        #pragma unroll
        for (int w = 0; w < 8; w++) {
            int gw = sg[w];
            if (gw != cur) {
                if (cur >= 0) {
                    atomicAdd(&g_gsum[cur * 64 + c0], a0);
                    atomicAdd(&g_gsum[cur * 64 + c0 + 1], a1);
                    if (lane == 0) atomicAdd(&g_gcnt[cur], cnt);
                }
                a0 = 0.f; a1 = 0.f; cnt = 0; cur = gw;
            }
            if (gw >= 0) { a0 += sv[w][c0]; a1 += sv[w][c0 + 1]; cnt++; }
        }
        if (cur >= 0) {
            atomicAdd(&g_gsum[cur * 64 + c0], a0);
            atomicAdd(&g_gsum[cur * 64 + c0 + 1], a1);
            if (lane == 0) atomicAdd(&g_gcnt[cur], cnt);
        }
    }
}

__global__ void classifier_kernel(const float* __restrict__ Wc1, const float* __restrict__ bc1,
                                  const float* __restrict__ Wc2, const float* __restrict__ bc2,
                                  const float* __restrict__ Wc3, const float* __restrict__ bc3,
                                  const float* __restrict__ Wc4, const float* __restrict__ bc4,
                                  float* __restrict__ out) {
    int g = blockIdx.x * blockDim.x + threadIdx.x;
    if (g >= NG) return;
    float inv = 1.f / fmaxf((float)g_gcnt[g], 1.f);
    float h[64];
    #pragma unroll
    for (int j = 0; j < 64; j++) h[j] = g_gsum[g * 64 + j] * inv;
    float t1[18];
    for (int j = 0; j < 18; j++) {
        float s = bc1[j];
        for (int k = 0; k < 64; k++) s += h[k] * Wc1[k * 18 + j];
        t1[j] = s;
    }
    float t2[12];
    for (int j = 0; j < 12; j++) {
        float s = bc2[j];
        for (int k = 0; k < 18; k++) s += t1[k] * Wc2[k * 12 + j];
        t2[j] = s;
    }
    float t3[6];
    for (int j = 0; j < 6; j++) {
        float s = bc3[j];
        for (int k = 0; k < 12; k++) s += t2[k] * Wc3[k * 6 + j];
        t3[j] = s;
    }
    for (int j = 0; j < 2; j++) {
        float s = bc4[j];
        for (int k = 0; k < 6; k++) s += t3[k] * Wc4[k * 2 + j];
        out[g * 2 + j] = s;
    }
}

// ---------------------------------------------------------------------------
extern "C" void kernel_launch(void* const* d_in, const int* in_sizes, int n_in,
                              void* d_out, int out_size) {
    const float* x   = (const float*)d_in[0];
    const int*   src = (const int*)d_in[1];
    const int*   dst = (const int*)d_in[2];
    const int*   gid = (const int*)d_in[3];
    const float* W1  = (const float*)d_in[4];
    const float* b1  = (const float*)d_in[5];
    const float* W2  = (const float*)d_in[6];
    const float* b2  = (const float*)d_in[7];
    const float* Wc1 = (const float*)d_in[8];
    const float* bc1 = (const float*)d_in[9];
    const float* Wc2 = (const float*)d_in[10];
    const float* bc2 = (const float*)d_in[11];
    const float* Wc3 = (const float*)d_in[12];
    const float* bc3 = (const float*)d_in[13];
    const float* Wc4 = (const float*)d_in[14];
    const float* bc4 = (const float*)d_in[15];
    float* out = (float*)d_out;

    float *p_agg1, *p_h2in, *p_rin, *p_rout;
    cudaGetSymbolAddress((void**)&p_agg1, g_agg1);
    cudaGetSymbolAddress((void**)&p_h2in, g_h2in);
    cudaGetSymbolAddress((void**)&p_rin,  g_rin);
    cudaGetSymbolAddress((void**)&p_rout, g_rout);

    static int smem_set = 0;
    const int fused_smem = FUSED_SMEM_FLOATS * 4;
    if (!smem_set) {
        cudaFuncSetAttribute(gemm_fused_kernel,
                             cudaFuncAttributeMaxDynamicSharedMemorySize, fused_smem);
        smem_set = 1;
    }

    zero_small_kernel<<<256, 256>>>();
    degree_kernel<<<(NE + 255) / 256, 256>>>(src, dst);
    finalize_deg_kernel<<<(NN + 255) / 256, 256>>>();

    // CSR build (dst-major)
    scanA_kernel<<<NB, 1024>>>();
    scanB_kernel<<<1, 128>>>();
    scanC_kernel<<<NB, 1024>>>();
    scatter_kernel<<<(NE + 255) / 256, 256>>>(src, dst);

    // layer 1 gather
    agg1_kernel<<<(NN * 32 + 255) / 256, 256>>>(x);

    // fused: h2in = rout * ( relu(rin*(agg1@W1)+b1) @ W2 )
    gemm_fused_kernel<<<(NN + 63) / 64, 256, fused_smem>>>(
        p_agg1, W1, W2, p_rin, b1, p_rout, p_h2in, NN);

    // layer 2 gather + pool
    agg2_pool_kernel<<<(NN + 7) / 8, 256>>>(gid, b2);

    classifier_kernel<<<(NG + 255) / 256, 256>>>(Wc1, bc1, Wc2, bc2, Wc3, bc3, Wc4, bc4, out);
}

// round 7
// speedup vs baseline: 1.6233x; 1.0687x over previous
#include <cuda_runtime.h>
#include <cuda_fp16.h>

#define NN 100000
#define NE 1600000
#define NG 512
#define NB 98   // ceil(NN/1024)

// ---- scratch (device globals; no allocation allowed) ----
__device__ int    g_degout[NN];
__device__ int    g_degin[NN];
__device__ float  g_rout[NN];
__device__ float  g_rin[NN];
__device__ int    g_rowptr[NN + 1];
__device__ int    g_cur[NN];
__device__ int    g_partial[NB];
__device__ int    g_base[NB];
__device__ int    g_csrc[NE];
__device__ __half g_xs[NN * 128];    // fp16(x * rout), 25.6 MB
__device__ float  g_agg1[NN * 128];  // 51.2 MB
__device__ __half g_h2in[NN * 64];   // 12.8 MB
__device__ float  g_gsum[NG * 64];
__device__ int    g_gcnt[NG];

// ---------------------------------------------------------------------------
__global__ void zero_small_kernel() {
    int i = blockIdx.x * blockDim.x + threadIdx.x;
    int stride = gridDim.x * blockDim.x;
    for (int j = i; j < NN; j += stride) { g_degout[j] = 0; g_degin[j] = 0; }
    for (int j = i; j < NG * 64; j += stride) g_gsum[j] = 0.f;
    for (int j = i; j < NG; j += stride) g_gcnt[j] = 0;
}

__global__ void degree_kernel(const int* __restrict__ src, const int* __restrict__ dst) {
    int e = blockIdx.x * blockDim.x + threadIdx.x;
    if (e < NE) {
        atomicAdd(&g_degout[src[e]], 1);
        atomicAdd(&g_degin[dst[e]], 1);
    }
}

__global__ void finalize_deg_kernel() {
    int i = blockIdx.x * blockDim.x + threadIdx.x;
    if (i < NN) {
        g_rout[i] = rsqrtf((float)max(g_degout[i], 1));
        g_rin[i]  = rsqrtf((float)max(g_degin[i], 1));
    }
}

// xs[n][d] = fp16( x[n][d] * rout[n] )
__global__ void xscale_kernel(const float* __restrict__ x) {
    int i = blockIdx.x * blockDim.x + threadIdx.x;   // float4 index
    int total = NN * 128 / 4;
    if (i >= total) return;
    int node = i >> 5;
    float r = g_rout[node];
    float4 v = ((const float4*)x)[i];
    __half2 h0 = __floats2half2_rn(v.x * r, v.y * r);
    __half2 h1 = __floats2half2_rn(v.z * r, v.w * r);
    ((uint2*)g_xs)[i] = make_uint2(*(unsigned*)&h0, *(unsigned*)&h1);
}

// ---- 3-phase exclusive scan of g_degin -> g_rowptr -------------------------
__global__ void scanA_kernel() {
    __shared__ int sh[1024];
    int idx = blockIdx.x * 1024 + threadIdx.x;
    sh[threadIdx.x] = (idx < NN) ? g_degin[idx] : 0;
    __syncthreads();
    for (int off = 512; off > 0; off >>= 1) {
        if (threadIdx.x < off) sh[threadIdx.x] += sh[threadIdx.x + off];
        __syncthreads();
    }
    if (threadIdx.x == 0) g_partial[blockIdx.x] = sh[0];
}

__global__ void scanB_kernel() {
    __shared__ int sh[128];
    int t = threadIdx.x;
    sh[t] = (t < NB) ? g_partial[t] : 0;
    __syncthreads();
    if (t == 0) {
        int run = 0;
        for (int b = 0; b < NB; b++) { int v = sh[b]; sh[b] = run; run += v; }
        g_rowptr[NN] = run;
    }
    __syncthreads();
    if (t < NB) g_base[t] = sh[t];
}

__global__ void scanC_kernel() {    // warp-shuffle scan, 98 blocks x 1024
    __shared__ int warpsum[32];
    int tid = threadIdx.x;
    int idx = blockIdx.x * 1024 + tid;
    int lane = tid & 31, w = tid >> 5;
    int v = (idx < NN) ? g_degin[idx] : 0;
    int s = v;
    #pragma unroll
    for (int o = 1; o < 32; o <<= 1) {
        int t = __shfl_up_sync(0xffffffffu, s, o);
        if (lane >= o) s += t;
    }
    if (lane == 31) warpsum[w] = s;
    __syncthreads();
    if (w == 0) {
        int ws = warpsum[lane];
        #pragma unroll
        for (int o = 1; o < 32; o <<= 1) {
            int t = __shfl_up_sync(0xffffffffu, ws, o);
            if (lane >= o) ws += t;
        }
        warpsum[lane] = ws;
    }
    __syncthreads();
    int excl = s - v + (w > 0 ? warpsum[w - 1] : 0) + g_base[blockIdx.x];
    if (idx < NN) {
        g_rowptr[idx] = excl;
        g_cur[idx] = excl;
    }
}

__global__ void scatter_kernel(const int* __restrict__ src, const int* __restrict__ dst) {
    int e = blockIdx.x * blockDim.x + threadIdx.x;
    if (e < NE) {
        int pos = atomicAdd(&g_cur[dst[e]], 1);
        g_csrc[pos] = src[e];
    }
}

// ---- layer-1 aggregation: warp per dst node, fp16 gather, fp32 accumulate --
__global__ void agg1_kernel() {
    int node = (blockIdx.x * blockDim.x + threadIdx.x) >> 5;
    if (node >= NN) return;
    int lane = threadIdx.x & 31;   // lane handles dims 4*lane..4*lane+3
    int beg = g_rowptr[node], end = g_rowptr[node + 1];
    float4 acc = make_float4(0.f, 0.f, 0.f, 0.f);
    int j = beg;
    for (; j + 3 < end; j += 4) {
        int s0 = g_csrc[j],     s1 = g_csrc[j + 1];
        int s2 = g_csrc[j + 2], s3 = g_csrc[j + 3];
        uint2 r0 = ((const uint2*)(g_xs + (size_t)s0 * 128))[lane];
        uint2 r1 = ((const uint2*)(g_xs + (size_t)s1 * 128))[lane];
        uint2 r2 = ((const uint2*)(g_xs + (size_t)s2 * 128))[lane];
        uint2 r3 = ((const uint2*)(g_xs + (size_t)s3 * 128))[lane];
        float2 a0 = __half22float2(*(__half2*)&r0.x), b0 = __half22float2(*(__half2*)&r0.y);
        float2 a1 = __half22float2(*(__half2*)&r1.x), b1 = __half22float2(*(__half2*)&r1.y);
        float2 a2 = __half22float2(*(__half2*)&r2.x), b2 = __half22float2(*(__half2*)&r2.y);
        float2 a3 = __half22float2(*(__half2*)&r3.x), b3 = __half22float2(*(__half2*)&r3.y);
        acc.x += a0.x + a1.x + a2.x + a3.x;
        acc.y += a0.y + a1.y + a2.y + a3.y;
        acc.z += b0.x + b1.x + b2.x + b3.x;
        acc.w += b0.y + b1.y + b2.y + b3.y;
    }
    for (; j < end; j++) {
        int s = g_csrc[j];
        uint2 r = ((const uint2*)(g_xs + (size_t)s * 128))[lane];
        float2 a = __half22float2(*(__half2*)&r.x), b = __half22float2(*(__half2*)&r.y);
        acc.x += a.x; acc.y += a.y; acc.z += b.x; acc.w += b.y;
    }
    ((float4*)(g_agg1 + (size_t)node * 128))[lane] = acc;
}

// ---- fused TF32 double-GEMM --------------------------------------------------
// h2in = fp16( rout ⊙ ( relu( rin ⊙ (agg1 @ W1) + b1 ) @ W2 ) )
__device__ __forceinline__ float tf32r(float x) {
    float r;
    asm("cvt.rna.tf32.f32 %0, %1;" : "=f"(r) : "f"(x));
    return r;
}

#define MMA_TF32(c, a0, a1, a2, a3, b0, b1)                                   \
    asm volatile("mma.sync.aligned.m16n8k8.row.col.f32.tf32.tf32.f32 "        \
                 "{%0,%1,%2,%3}, {%4,%5,%6,%7}, {%8,%9}, {%0,%1,%2,%3};"      \
                 : "+f"(c[0]), "+f"(c[1]), "+f"(c[2]), "+f"(c[3])             \
                 : "r"(a0), "r"(a1), "r"(a2), "r"(a3), "r"(b0), "r"(b1))

#define FUSED_SMEM_FLOATS (4*64*36 + 4*64*36 + 2*64*36 + 2*64*36)

__global__ void gemm_fused_kernel(const float* __restrict__ A,   // agg1 [M,128]
                                  const float* __restrict__ W1,  // [128,256]
                                  const float* __restrict__ W2,  // [256,64]
                                  const float* __restrict__ rin,
                                  const float* __restrict__ b1,
                                  const float* __restrict__ rout,
                                  __half* __restrict__ Cout,     // h2in [M,64]
                                  int M) {
    extern __shared__ float sm[];
    float* As  = sm;                     // [4 kchunk][64 row][36]
    float* Bs1 = As + 4 * 64 * 36;       // [4 kchunk][64 col][36]
    float* Bs2 = Bs1 + 4 * 64 * 36;      // [2 kchunk][64 col][36]
    float* Hs  = Bs2 + 2 * 64 * 36;      // [2 kchunk][64 row][36]

    int tid = threadIdx.x;
    int warp = tid >> 5, lane = tid & 31;
    int g = lane >> 2, q = lane & 3;
    int wm = warp & 1, wn = warp >> 1;
    int rowBase = blockIdx.x * 64;

    float rs0[2], rs1[2], ro0[2], ro1[2];
    #pragma unroll
    for (int mt = 0; mt < 2; mt++) {
        int r = rowBase + wm * 32 + mt * 16 + g;
        rs0[mt] = (r < M) ? rin[r] : 0.f;
        ro0[mt] = (r < M) ? rout[r] : 0.f;
        rs1[mt] = (r + 8 < M) ? rin[r + 8] : 0.f;
        ro1[mt] = (r + 8 < M) ? rout[r + 8] : 0.f;
    }

    // prologue: A block [64 x 128] -> As (tf32, permuted), kept all kernel
    #pragma unroll
    for (int kc = 0; kc < 4; kc++) {
        #pragma unroll
        for (int it = 0; it < 2; it++) {
            int idx = tid + it * 256;
            int row = idx >> 3;
            int k4 = (idx & 7) * 4;
            int gr = rowBase + row;
            float4 v = make_float4(0.f, 0.f, 0.f, 0.f);
            if (gr < M) v = *(const float4*)(A + (size_t)gr * 128 + kc * 32 + k4);
            int s = k4 >> 2;
            float* p = As + (kc * 64 + row) * 36;
            p[s]      = tf32r(v.x);
            p[8 + s]  = tf32r(v.y);
            p[16 + s] = tf32r(v.z);
            p[24 + s] = tf32r(v.w);
        }
    }

    float c2[2][2][4] = {};

    for (int qtr = 0; qtr < 4; qtr++) {
        // W1 tile: k=0..127, cols qtr*64..+64 -> Bs1
        #pragma unroll
        for (int kc = 0; kc < 4; kc++) {
            #pragma unroll
            for (int it = 0; it < 2; it++) {
                int idx = tid + it * 256;
                int krow = idx >> 4;
                int col = (idx & 15) * 4;
                float4 v = *(const float4*)(W1 + (size_t)(kc * 32 + krow) * 256 + qtr * 64 + col);
                int s = ((krow & 3) << 3) + (krow >> 2);
                Bs1[(kc * 64 + col + 0) * 36 + s] = tf32r(v.x);
                Bs1[(kc * 64 + col + 1) * 36 + s] = tf32r(v.y);
                Bs1[(kc * 64 + col + 2) * 36 + s] = tf32r(v.z);
                Bs1[(kc * 64 + col + 3) * 36 + s] = tf32r(v.w);
            }
        }
        __syncthreads();

        // MMA1: c1 = A_tile @ W1_quarter
        float c1[2][2][4] = {};
        #pragma unroll
        for (int kc = 0; kc < 4; kc++) {
            #pragma unroll
            for (int ks2 = 0; ks2 < 2; ks2++) {
                uint4 alo[2], ahi[2], bf[2];
                #pragma unroll
                for (int mt = 0; mt < 2; mt++) {
                    const float* p = As + (kc * 64 + wm * 32 + mt * 16 + g) * 36 + q * 8 + ks2 * 4;
                    alo[mt] = *(const uint4*)p;
                    ahi[mt] = *(const uint4*)(p + 8 * 36);
                }
                #pragma unroll
                for (int nt = 0; nt < 2; nt++)
                    bf[nt] = *(const uint4*)(Bs1 + (kc * 64 + wn * 16 + nt * 8 + g) * 36 + q * 8 + ks2 * 4);
                #pragma unroll
                for (int mt = 0; mt < 2; mt++)
                    #pragma unroll
                    for (int nt = 0; nt < 2; nt++) {
                        MMA_TF32(c1[mt][nt], alo[mt].x, ahi[mt].x, alo[mt].y, ahi[mt].y,
                                 bf[nt].x, bf[nt].y);
                        MMA_TF32(c1[mt][nt], alo[mt].z, ahi[mt].z, alo[mt].w, ahi[mt].w,
                                 bf[nt].z, bf[nt].w);
                    }
            }
        }

        // epilogue1 -> Hs (tf32, MMA2-A layout)
        #pragma unroll
        for (int nt = 0; nt < 2; nt++) {
            int cL0 = wn * 16 + nt * 8 + 2 * q;
            float2 bb = *(const float2*)(b1 + qtr * 64 + cL0);
            int chunk = cL0 >> 5;
            int c32 = cL0 & 31;
            int slot0 = (c32 & 3) * 8 + (c32 >> 2);
            #pragma unroll
            for (int mt = 0; mt < 2; mt++) {
                int r0 = wm * 32 + mt * 16 + g;
                float v00 = fmaxf(c1[mt][nt][0] * rs0[mt] + bb.x, 0.f);
                float v01 = fmaxf(c1[mt][nt][1] * rs0[mt] + bb.y, 0.f);
                float v10 = fmaxf(c1[mt][nt][2] * rs1[mt] + bb.x, 0.f);
                float v11 = fmaxf(c1[mt][nt][3] * rs1[mt] + bb.y, 0.f);
                float* hp0 = Hs + (chunk * 64 + r0) * 36;
                float* hp1 = hp0 + 8 * 36;
                hp0[slot0]     = tf32r(v00);
                hp0[slot0 + 8] = tf32r(v01);
                hp1[slot0]     = tf32r(v10);
                hp1[slot0 + 8] = tf32r(v11);
            }
        }

        // W2 tile: rows qtr*64..+64 -> Bs2
        #pragma unroll
        for (int cc = 0; cc < 2; cc++) {
            #pragma unroll
            for (int it = 0; it < 2; it++) {
                int idx = tid + it * 256;
                int krow = idx >> 4;
                int col = (idx & 15) * 4;
                float4 v = *(const float4*)(W2 + (size_t)(qtr * 64 + cc * 32 + krow) * 64 + col);
                int s = ((krow & 3) << 3) + (krow >> 2);
                Bs2[(cc * 64 + col + 0) * 36 + s] = tf32r(v.x);
                Bs2[(cc * 64 + col + 1) * 36 + s] = tf32r(v.y);
                Bs2[(cc * 64 + col + 2) * 36 + s] = tf32r(v.z);
                Bs2[(cc * 64 + col + 3) * 36 + s] = tf32r(v.w);
            }
        }
        __syncthreads();

        // MMA2: c2 += h1_quarter @ W2_quarter
        #pragma unroll
        for (int cc = 0; cc < 2; cc++) {
            #pragma unroll
            for (int ks2 = 0; ks2 < 2; ks2++) {
                uint4 alo[2], ahi[2], bf[2];
                #pragma unroll
                for (int mt = 0; mt < 2; mt++) {
                    const float* p = Hs + (cc * 64 + wm * 32 + mt * 16 + g) * 36 + q * 8 + ks2 * 4;
                    alo[mt] = *(const uint4*)p;
                    ahi[mt] = *(const uint4*)(p + 8 * 36);
                }
                #pragma unroll
                for (int nt = 0; nt < 2; nt++)
                    bf[nt] = *(const uint4*)(Bs2 + (cc * 64 + wn * 16 + nt * 8 + g) * 36 + q * 8 + ks2 * 4);
                #pragma unroll
                for (int mt = 0; mt < 2; mt++)
                    #pragma unroll
                    for (int nt = 0; nt < 2; nt++) {
                        MMA_TF32(c2[mt][nt], alo[mt].x, ahi[mt].x, alo[mt].y, ahi[mt].y,
                                 bf[nt].x, bf[nt].y);
                        MMA_TF32(c2[mt][nt], alo[mt].z, ahi[mt].z, alo[mt].w, ahi[mt].w,
                                 bf[nt].z, bf[nt].w);
                    }
            }
        }
        __syncthreads();
    }

    // final epilogue: h2in = fp16(rout * c2)
    #pragma unroll
    for (int mt = 0; mt < 2; mt++) {
        int r0 = rowBase + wm * 32 + mt * 16 + g;
        #pragma unroll
        for (int nt = 0; nt < 2; nt++) {
            int c0 = wn * 16 + nt * 8 + 2 * q;
            if (r0 < M)
                *(__half2*)(Cout + (size_t)r0 * 64 + c0) =
                    __floats2half2_rn(c2[mt][nt][0] * ro0[mt], c2[mt][nt][1] * ro0[mt]);
            if (r0 + 8 < M)
                *(__half2*)(Cout + (size_t)(r0 + 8) * 64 + c0) =
                    __floats2half2_rn(c2[mt][nt][2] * ro1[mt], c2[mt][nt][3] * ro1[mt]);
        }
    }
}

// ---- layer-2 aggregation fused with mean-pool reduction (fp16 gather) ------
__global__ void agg2_pool_kernel(const int* __restrict__ gid, const float* __restrict__ b2) {
    __shared__ float sv[8][64];
    __shared__ int sg[8];
    int wid = threadIdx.x >> 5, lane = threadIdx.x & 31;
    int node = blockIdx.x * 8 + wid;
    float2 acc = make_float2(0.f, 0.f);
    int gv = -1;
    if (node < NN) {
        int beg = g_rowptr[node], end = g_rowptr[node + 1];
        int j = beg;
        for (; j + 3 < end; j += 4) {
            int s0 = g_csrc[j],     s1 = g_csrc[j + 1];
            int s2 = g_csrc[j + 2], s3 = g_csrc[j + 3];
            float2 v0 = __half22float2(((const __half2*)(g_h2in + (size_t)s0 * 64))[lane]);
            float2 v1 = __half22float2(((const __half2*)(g_h2in + (size_t)s1 * 64))[lane]);
            float2 v2 = __half22float2(((const __half2*)(g_h2in + (size_t)s2 * 64))[lane]);
            float2 v3 = __half22float2(((const __half2*)(g_h2in + (size_t)s3 * 64))[lane]);
            acc.x += v0.x + v1.x + v2.x + v3.x;
            acc.y += v0.y + v1.y + v2.y + v3.y;
        }
        for (; j < end; j++) {
            int s = g_csrc[j];
            float2 v = __half22float2(((const __half2*)(g_h2in + (size_t)s * 64))[lane]);
            acc.x += v.x; acc.y += v.y;
        }
        float ri = g_rin[node];
        float2 bb = ((const float2*)b2)[lane];
        acc.x = fmaxf(acc.x * ri + bb.x, 0.f);
        acc.y = fmaxf(acc.y * ri + bb.y, 0.f);
        gv = gid[node];
    }
    sv[wid][lane * 2]     = acc.x;
    sv[wid][lane * 2 + 1] = acc.y;
    if (lane == 0) sg[wid] = gv;
    __syncthreads();

    if (wid == 0) {
        int c0 = lane * 2;
        float a0 = 0.f, a1 = 0.f;
        int cnt = 0;
        int cur = sg[0];
        #pragma unroll
        for (int w = 0; w < 8; w++) {
            int gw = sg[w];
            if (gw != cur) {
                if (cur >= 0) {
                    atomicAdd(&g_gsum[cur * 64 + c0], a0);
                    atomicAdd(&g_gsum[cur * 64 + c0 + 1], a1);
                    if (lane == 0) atomicAdd(&g_gcnt[cur], cnt);
                }
                a0 = 0.f; a1 = 0.f; cnt = 0; cur = gw;
            }
            if (gw >= 0) { a0 += sv[w][c0]; a1 += sv[w][c0 + 1]; cnt++; }
        }
        if (cur >= 0) {
            atomicAdd(&g_gsum[cur * 64 + c0], a0);
            atomicAdd(&g_gsum[cur * 64 + c0 + 1], a1);
            if (lane == 0) atomicAdd(&g_gcnt[cur], cnt);
        }
    }
}

__global__ void classifier_kernel(const float* __restrict__ Wc1, const float* __restrict__ bc1,
                                  const float* __restrict__ Wc2, const float* __restrict__ bc2,
                                  const float* __restrict__ Wc3, const float* __restrict__ bc3,
                                  const float* __restrict__ Wc4, const float* __restrict__ bc4,
                                  float* __restrict__ out) {
    int g = blockIdx.x * blockDim.x + threadIdx.x;
    if (g >= NG) return;
    float inv = 1.f / fmaxf((float)g_gcnt[g], 1.f);
    float h[64];
    #pragma unroll
    for (int j = 0; j < 64; j++) h[j] = g_gsum[g * 64 + j] * inv;
    float t1[18];
    for (int j = 0; j < 18; j++) {
        float s = bc1[j];
        for (int k = 0; k < 64; k++) s += h[k] * Wc1[k * 18 + j];
        t1[j] = s;
    }
    float t2[12];
    for (int j = 0; j < 12; j++) {
        float s = bc2[j];
        for (int k = 0; k < 18; k++) s += t1[k] * Wc2[k * 12 + j];
        t2[j] = s;
    }
    float t3[6];
    for (int j = 0; j < 6; j++) {
        float s = bc3[j];
        for (int k = 0; k < 12; k++) s += t2[k] * Wc3[k * 6 + j];
        t3[j] = s;
    }
    for (int j = 0; j < 2; j++) {
        float s = bc4[j];
        for (int k = 0; k < 6; k++) s += t3[k] * Wc4[k * 2 + j];
        out[g * 2 + j] = s;
    }
}

// ---------------------------------------------------------------------------
extern "C" void kernel_launch(void* const* d_in, const int* in_sizes, int n_in,
                              void* d_out, int out_size) {
    const float* x   = (const float*)d_in[0];
    const int*   src = (const int*)d_in[1];
    const int*   dst = (const int*)d_in[2];
    const int*   gid = (const int*)d_in[3];
    const float* W1  = (const float*)d_in[4];
    const float* b1  = (const float*)d_in[5];
    const float* W2  = (const float*)d_in[6];
    const float* b2  = (const float*)d_in[7];
    const float* Wc1 = (const float*)d_in[8];
    const float* bc1 = (const float*)d_in[9];
    const float* Wc2 = (const float*)d_in[10];
    const float* bc2 = (const float*)d_in[11];
    const float* Wc3 = (const float*)d_in[12];
    const float* bc3 = (const float*)d_in[13];
    const float* Wc4 = (const float*)d_in[14];
    const float* bc4 = (const float*)d_in[15];
    float* out = (float*)d_out;

    float *p_agg1, *p_rin, *p_rout;
    __half* p_h2in;
    cudaGetSymbolAddress((void**)&p_agg1, g_agg1);
    cudaGetSymbolAddress((void**)&p_h2in, g_h2in);
    cudaGetSymbolAddress((void**)&p_rin,  g_rin);
    cudaGetSymbolAddress((void**)&p_rout, g_rout);

    static int smem_set = 0;
    const int fused_smem = FUSED_SMEM_FLOATS * 4;
    if (!smem_set) {
        cudaFuncSetAttribute(gemm_fused_kernel,
                             cudaFuncAttributeMaxDynamicSharedMemorySize, fused_smem);
        smem_set = 1;
    }

    zero_small_kernel<<<256, 256>>>();
    degree_kernel<<<(NE + 255) / 256, 256>>>(src, dst);
    finalize_deg_kernel<<<(NN + 255) / 256, 256>>>();

    // pre-scale + fp16 pack x
    xscale_kernel<<<(NN * 32 + 255) / 256, 256>>>(x);

    // CSR build (dst-major)
    scanA_kernel<<<NB, 1024>>>();
    scanB_kernel<<<1, 128>>>();
    scanC_kernel<<<NB, 1024>>>();
    scatter_kernel<<<(NE + 255) / 256, 256>>>(src, dst);

    // layer 1 gather (fp16 source, fp32 accumulate)
    agg1_kernel<<<(NN * 32 + 255) / 256, 256>>>();

    // fused: h2in = fp16( rout * ( relu(rin*(agg1@W1)+b1) @ W2 ) )
    gemm_fused_kernel<<<(NN + 63) / 64, 256, fused_smem>>>(
        p_agg1, W1, W2, p_rin, b1, p_rout, p_h2in, NN);

    // layer 2 gather + pool (fp16 gather)
    agg2_pool_kernel<<<(NN + 7) / 8, 256>>>(gid, b2);

    classifier_kernel<<<(NG + 255) / 256, 256>>>(Wc1, bc1, Wc2, bc2, Wc3, bc3, Wc4, bc4, out);
}

// round 8
// speedup vs baseline: 2.3071x; 1.4213x over previous
#include <cuda_runtime.h>
#include <cuda_fp16.h>

#define NN 100000
#define NE 1600000
#define NG 512
#define NB 98   // ceil(NN/1024)

// ---- scratch (device globals; no allocation allowed) ----
__device__ int    g_degout[NN];
__device__ int    g_degin[NN];
__device__ float  g_rout[NN];
__device__ float  g_rin[NN];
__device__ int    g_rowptr[NN + 1];
__device__ int    g_cur[NN];
__device__ int    g_partial[NB];
__device__ int    g_base[NB];
__device__ int    g_csrc[NE];
__device__ __half g_xs[NN * 128];     // fp16(x * rout), 25.6 MB
__device__ __half g_agg1h[NN * 128];  // fp16 aggregation, 25.6 MB
__device__ __half g_h2in[NN * 64];    // 12.8 MB
__device__ float  g_gsum[NG * 64];
__device__ int    g_gcnt[NG];

// ---------------------------------------------------------------------------
__global__ void zero_small_kernel() {
    int i = blockIdx.x * blockDim.x + threadIdx.x;
    int stride = gridDim.x * blockDim.x;
    for (int j = i; j < NN; j += stride) { g_degout[j] = 0; g_degin[j] = 0; }
    for (int j = i; j < NG * 64; j += stride) g_gsum[j] = 0.f;
    for (int j = i; j < NG; j += stride) g_gcnt[j] = 0;
}

__global__ void degree_kernel(const int* __restrict__ src, const int* __restrict__ dst) {
    int e = blockIdx.x * blockDim.x + threadIdx.x;
    if (e < NE) {
        atomicAdd(&g_degout[src[e]], 1);
        atomicAdd(&g_degin[dst[e]], 1);
    }
}

__global__ void finalize_deg_kernel() {
    int i = blockIdx.x * blockDim.x + threadIdx.x;
    if (i < NN) {
        g_rout[i] = rsqrtf((float)max(g_degout[i], 1));
        g_rin[i]  = rsqrtf((float)max(g_degin[i], 1));
    }
}

// xs[n][d] = fp16( x[n][d] * rout[n] )
__global__ void xscale_kernel(const float* __restrict__ x) {
    int i = blockIdx.x * blockDim.x + threadIdx.x;   // float4 index
    int total = NN * 128 / 4;
    if (i >= total) return;
    int node = i >> 5;
    float r = g_rout[node];
    float4 v = ((const float4*)x)[i];
    __half2 h0 = __floats2half2_rn(v.x * r, v.y * r);
    __half2 h1 = __floats2half2_rn(v.z * r, v.w * r);
    ((uint2*)g_xs)[i] = make_uint2(*(unsigned*)&h0, *(unsigned*)&h1);
}

// ---- 3-phase exclusive scan of g_degin -> g_rowptr -------------------------
__global__ void scanA_kernel() {
    __shared__ int sh[1024];
    int idx = blockIdx.x * 1024 + threadIdx.x;
    sh[threadIdx.x] = (idx < NN) ? g_degin[idx] : 0;
    __syncthreads();
    for (int off = 512; off > 0; off >>= 1) {
        if (threadIdx.x < off) sh[threadIdx.x] += sh[threadIdx.x + off];
        __syncthreads();
    }
    if (threadIdx.x == 0) g_partial[blockIdx.x] = sh[0];
}

__global__ void scanB_kernel() {
    __shared__ int sh[128];
    int t = threadIdx.x;
    sh[t] = (t < NB) ? g_partial[t] : 0;
    __syncthreads();
    if (t == 0) {
        int run = 0;
        for (int b = 0; b < NB; b++) { int v = sh[b]; sh[b] = run; run += v; }
        g_rowptr[NN] = run;
    }
    __syncthreads();
    if (t < NB) g_base[t] = sh[t];
}

__global__ void scanC_kernel() {    // warp-shuffle scan
    __shared__ int warpsum[32];
    int tid = threadIdx.x;
    int idx = blockIdx.x * 1024 + tid;
    int lane = tid & 31, w = tid >> 5;
    int v = (idx < NN) ? g_degin[idx] : 0;
    int s = v;
    #pragma unroll
    for (int o = 1; o < 32; o <<= 1) {
        int t = __shfl_up_sync(0xffffffffu, s, o);
        if (lane >= o) s += t;
    }
    if (lane == 31) warpsum[w] = s;
    __syncthreads();
    if (w == 0) {
        int ws = warpsum[lane];
        #pragma unroll
        for (int o = 1; o < 32; o <<= 1) {
            int t = __shfl_up_sync(0xffffffffu, ws, o);
            if (lane >= o) ws += t;
        }
        warpsum[lane] = ws;
    }
    __syncthreads();
    int excl = s - v + (w > 0 ? warpsum[w - 1] : 0) + g_base[blockIdx.x];
    if (idx < NN) {
        g_rowptr[idx] = excl;
        g_cur[idx] = excl;
    }
}

__global__ void scatter_kernel(const int* __restrict__ src, const int* __restrict__ dst) {
    int e = blockIdx.x * blockDim.x + threadIdx.x;
    if (e < NE) {
        int pos = atomicAdd(&g_cur[dst[e]], 1);
        g_csrc[pos] = src[e];
    }
}

// ---- layer-1 aggregation: warp per dst, fp16 in, fp32 acc, fp16 out --------
__global__ void agg1_kernel() {
    int node = (blockIdx.x * blockDim.x + threadIdx.x) >> 5;
    if (node >= NN) return;
    int lane = threadIdx.x & 31;   // dims 4*lane..4*lane+3
    int beg = g_rowptr[node], end = g_rowptr[node + 1];
    float4 acc = make_float4(0.f, 0.f, 0.f, 0.f);
    int j = beg;
    for (; j + 3 < end; j += 4) {
        int s0 = g_csrc[j],     s1 = g_csrc[j + 1];
        int s2 = g_csrc[j + 2], s3 = g_csrc[j + 3];
        uint2 r0 = ((const uint2*)(g_xs + (size_t)s0 * 128))[lane];
        uint2 r1 = ((const uint2*)(g_xs + (size_t)s1 * 128))[lane];
        uint2 r2 = ((const uint2*)(g_xs + (size_t)s2 * 128))[lane];
        uint2 r3 = ((const uint2*)(g_xs + (size_t)s3 * 128))[lane];
        float2 a0 = __half22float2(*(__half2*)&r0.x), b0 = __half22float2(*(__half2*)&r0.y);
        float2 a1 = __half22float2(*(__half2*)&r1.x), b1 = __half22float2(*(__half2*)&r1.y);
        float2 a2 = __half22float2(*(__half2*)&r2.x), b2 = __half22float2(*(__half2*)&r2.y);
        float2 a3 = __half22float2(*(__half2*)&r3.x), b3 = __half22float2(*(__half2*)&r3.y);
        acc.x += a0.x + a1.x + a2.x + a3.x;
        acc.y += a0.y + a1.y + a2.y + a3.y;
        acc.z += b0.x + b1.x + b2.x + b3.x;
        acc.w += b0.y + b1.y + b2.y + b3.y;
    }
    for (; j < end; j++) {
        int s = g_csrc[j];
        uint2 r = ((const uint2*)(g_xs + (size_t)s * 128))[lane];
        float2 a = __half22float2(*(__half2*)&r.x), b = __half22float2(*(__half2*)&r.y);
        acc.x += a.x; acc.y += a.y; acc.z += b.x; acc.w += b.y;
    }
    __half2 h0 = __floats2half2_rn(acc.x, acc.y);
    __half2 h1 = __floats2half2_rn(acc.z, acc.w);
    ((uint2*)(g_agg1h + (size_t)node * 128))[lane] = make_uint2(*(unsigned*)&h0, *(unsigned*)&h1);
}

// ---- fused FP16 double-GEMM ------------------------------------------------
// h2in = fp16( rout ⊙ ( relu( rin ⊙ (agg1h @ W1) + b1 ) @ W2 ) )
// mma.sync.m16n8k16.f32.f16.f16.f32 + ldmatrix. Block = 64 rows, 8 warps.
__device__ __forceinline__ unsigned smem_u32(const void* p) {
    return (unsigned)__cvta_generic_to_shared(p);
}
__device__ __forceinline__ void ldsm_x4(unsigned& r0, unsigned& r1, unsigned& r2, unsigned& r3,
                                        unsigned addr) {
    asm volatile("ldmatrix.sync.aligned.m8n8.x4.shared.b16 {%0,%1,%2,%3}, [%4];"
                 : "=r"(r0), "=r"(r1), "=r"(r2), "=r"(r3) : "r"(addr));
}
__device__ __forceinline__ void ldsm_x2t(unsigned& r0, unsigned& r1, unsigned addr) {
    asm volatile("ldmatrix.sync.aligned.m8n8.x2.trans.shared.b16 {%0,%1}, [%2];"
                 : "=r"(r0), "=r"(r1) : "r"(addr));
}
#define MMA_F16(c, a0, a1, a2, a3, b0, b1)                                    \
    asm volatile("mma.sync.aligned.m16n8k16.row.col.f32.f16.f16.f32 "         \
                 "{%0,%1,%2,%3}, {%4,%5,%6,%7}, {%8,%9}, {%0,%1,%2,%3};"      \
                 : "+f"(c[0]), "+f"(c[1]), "+f"(c[2]), "+f"(c[3])             \
                 : "r"(a0), "r"(a1), "r"(a2), "r"(a3), "r"(b0), "r"(b1))

// smem halves: As[64][136] | Bs1[128][72] | Bs2[64][72] | Hs[64][72]
#define AS_STRIDE 136
#define BS_STRIDE 72
#define OFF_AS  0
#define OFF_BS1 (64 * AS_STRIDE)
#define OFF_BS2 (OFF_BS1 + 128 * BS_STRIDE)
#define OFF_HS  (OFF_BS2 + 64 * BS_STRIDE)
#define FUSED_SMEM_HALVES (OFF_HS + 64 * BS_STRIDE)

__global__ void gemm_fused_kernel(const __half* __restrict__ A,  // agg1h [M,128]
                                  const float* __restrict__ W1,  // [128,256]
                                  const float* __restrict__ W2,  // [256,64]
                                  const float* __restrict__ rin,
                                  const float* __restrict__ b1,
                                  const float* __restrict__ rout,
                                  __half* __restrict__ Cout,     // h2in [M,64]
                                  int M) {
    extern __shared__ __half sm[];
    __half* As  = sm + OFF_AS;
    __half* Bs1 = sm + OFF_BS1;
    __half* Bs2 = sm + OFF_BS2;
    __half* Hs  = sm + OFF_HS;

    int tid = threadIdx.x;
    int warp = tid >> 5, lane = tid & 31;
    int g = lane >> 2, q = lane & 3;
    int wm = warp & 1, wn = warp >> 1;
    int rowBase = blockIdx.x * 64;
    int l16 = lane & 15, lh = lane >> 4;

    float rs0[2], rs1[2], ro0[2], ro1[2];
    #pragma unroll
    for (int mt = 0; mt < 2; mt++) {
        int r = rowBase + wm * 32 + mt * 16 + g;
        rs0[mt] = (r < M) ? rin[r] : 0.f;
        ro0[mt] = (r < M) ? rout[r] : 0.f;
        rs1[mt] = (r + 8 < M) ? rin[r + 8] : 0.f;
        ro1[mt] = (r + 8 < M) ? rout[r + 8] : 0.f;
    }

    // prologue: A block [64 x 128] fp16 -> As (plain layout, kept all kernel)
    #pragma unroll
    for (int it = 0; it < 4; it++) {
        int idx = tid + it * 256;        // uint4 index; 16 per row
        int row = idx >> 4;
        int c8 = (idx & 15) * 8;
        int gr = rowBase + row;
        uint4 v = make_uint4(0u, 0u, 0u, 0u);
        if (gr < M) v = *(const uint4*)(A + (size_t)gr * 128 + c8);
        *(uint4*)(As + row * AS_STRIDE + c8) = v;
    }

    float c2[2][2][4] = {};

    for (int qtr = 0; qtr < 4; qtr++) {
        // W1 tile: [128 k][64 n] fp32 -> fp16 Bs1
        #pragma unroll
        for (int it = 0; it < 8; it++) {
            int idx = tid + it * 256;
            int krow = idx >> 4;
            int c4 = (idx & 15) * 4;
            float4 v = *(const float4*)(W1 + (size_t)krow * 256 + qtr * 64 + c4);
            __half2 h0 = __floats2half2_rn(v.x, v.y);
            __half2 h1 = __floats2half2_rn(v.z, v.w);
            *(uint2*)(Bs1 + krow * BS_STRIDE + c4) = make_uint2(*(unsigned*)&h0, *(unsigned*)&h1);
        }
        __syncthreads();

        // MMA1: c1 = A_tile @ W1_quarter  (64x64, K=128)
        float c1[2][2][4] = {};
        #pragma unroll
        for (int ks = 0; ks < 8; ks++) {
            unsigned a[2][4], b[2][2];
            #pragma unroll
            for (int mt = 0; mt < 2; mt++)
                ldsm_x4(a[mt][0], a[mt][1], a[mt][2], a[mt][3],
                        smem_u32(As + (wm * 32 + mt * 16 + l16) * AS_STRIDE + ks * 16 + lh * 8));
            #pragma unroll
            for (int nt = 0; nt < 2; nt++)
                ldsm_x2t(b[nt][0], b[nt][1],
                         smem_u32(Bs1 + (ks * 16 + l16) * BS_STRIDE + wn * 16 + nt * 8));
            #pragma unroll
            for (int mt = 0; mt < 2; mt++)
                #pragma unroll
                for (int nt = 0; nt < 2; nt++)
                    MMA_F16(c1[mt][nt], a[mt][0], a[mt][1], a[mt][2], a[mt][3],
                            b[nt][0], b[nt][1]);
        }

        // epilogue1: relu(rin*c1 + b1) -> Hs fp16 [64 row][64 col]
        #pragma unroll
        for (int nt = 0; nt < 2; nt++) {
            int cL0 = wn * 16 + nt * 8 + 2 * q;
            float2 bb = *(const float2*)(b1 + qtr * 64 + cL0);
            #pragma unroll
            for (int mt = 0; mt < 2; mt++) {
                int r0 = wm * 32 + mt * 16 + g;
                __half2 h0 = __floats2half2_rn(fmaxf(c1[mt][nt][0] * rs0[mt] + bb.x, 0.f),
                                               fmaxf(c1[mt][nt][1] * rs0[mt] + bb.y, 0.f));
                __half2 h1 = __floats2half2_rn(fmaxf(c1[mt][nt][2] * rs1[mt] + bb.x, 0.f),
                                               fmaxf(c1[mt][nt][3] * rs1[mt] + bb.y, 0.f));
                *(__half2*)(Hs + r0 * BS_STRIDE + cL0) = h0;
                *(__half2*)(Hs + (r0 + 8) * BS_STRIDE + cL0) = h1;
            }
        }

        // W2 tile: rows qtr*64..+64 [64 k][64 n] -> fp16 Bs2
        #pragma unroll
        for (int it = 0; it < 4; it++) {
            int idx = tid + it * 256;
            int krow = idx >> 4;
            int c4 = (idx & 15) * 4;
            float4 v = *(const float4*)(W2 + (size_t)(qtr * 64 + krow) * 64 + c4);
            __half2 h0 = __floats2half2_rn(v.x, v.y);
            __half2 h1 = __floats2half2_rn(v.z, v.w);
            *(uint2*)(Bs2 + krow * BS_STRIDE + c4) = make_uint2(*(unsigned*)&h0, *(unsigned*)&h1);
        }
        __syncthreads();

        // MMA2: c2 += h1_quarter @ W2_quarter  (64x64, K=64)
        #pragma unroll
        for (int ks = 0; ks < 4; ks++) {
            unsigned a[2][4], b[2][2];
            #pragma unroll
            for (int mt = 0; mt < 2; mt++)
                ldsm_x4(a[mt][0], a[mt][1], a[mt][2], a[mt][3],
                        smem_u32(Hs + (wm * 32 + mt * 16 + l16) * BS_STRIDE + ks * 16 + lh * 8));
            #pragma unroll
            for (int nt = 0; nt < 2; nt++)
                ldsm_x2t(b[nt][0], b[nt][1],
                         smem_u32(Bs2 + (ks * 16 + l16) * BS_STRIDE + wn * 16 + nt * 8));
            #pragma unroll
            for (int mt = 0; mt < 2; mt++)
                #pragma unroll
                for (int nt = 0; nt < 2; nt++)
                    MMA_F16(c2[mt][nt], a[mt][0], a[mt][1], a[mt][2], a[mt][3],
                            b[nt][0], b[nt][1]);
        }
        __syncthreads();   // all MMA2 reads done before next quarter's writes
    }

    // final epilogue: h2in = fp16(rout * c2)
    #pragma unroll
    for (int mt = 0; mt < 2; mt++) {
        int r0 = rowBase + wm * 32 + mt * 16 + g;
        #pragma unroll
        for (int nt = 0; nt < 2; nt++) {
            int c0 = wn * 16 + nt * 8 + 2 * q;
            if (r0 < M)
                *(__half2*)(Cout + (size_t)r0 * 64 + c0) =
                    __floats2half2_rn(c2[mt][nt][0] * ro0[mt], c2[mt][nt][1] * ro0[mt]);
            if (r0 + 8 < M)
                *(__half2*)(Cout + (size_t)(r0 + 8) * 64 + c0) =
                    __floats2half2_rn(c2[mt][nt][2] * ro1[mt], c2[mt][nt][3] * ro1[mt]);
        }
    }
}

// ---- layer-2 aggregation fused with mean-pool reduction (fp16 gather) ------
__global__ void agg2_pool_kernel(const int* __restrict__ gid, const float* __restrict__ b2) {
    __shared__ float sv[8][64];
    __shared__ int sg[8];
    int wid = threadIdx.x >> 5, lane = threadIdx.x & 31;
    int node = blockIdx.x * 8 + wid;
    float2 acc = make_float2(0.f, 0.f);
    int gv = -1;
    if (node < NN) {
        int beg = g_rowptr[node], end = g_rowptr[node + 1];
        int j = beg;
        for (; j + 3 < end; j += 4) {
            int s0 = g_csrc[j],     s1 = g_csrc[j + 1];
            int s2 = g_csrc[j + 2], s3 = g_csrc[j + 3];
            float2 v0 = __half22float2(((const __half2*)(g_h2in + (size_t)s0 * 64))[lane]);
            float2 v1 = __half22float2(((const __half2*)(g_h2in + (size_t)s1 * 64))[lane]);
            float2 v2 = __half22float2(((const __half2*)(g_h2in + (size_t)s2 * 64))[lane]);
            float2 v3 = __half22float2(((const __half2*)(g_h2in + (size_t)s3 * 64))[lane]);
            acc.x += v0.x + v1.x + v2.x + v3.x;
            acc.y += v0.y + v1.y + v2.y + v3.y;
        }
        for (; j < end; j++) {
            int s = g_csrc[j];
            float2 v = __half22float2(((const __half2*)(g_h2in + (size_t)s * 64))[lane]);
            acc.x += v.x; acc.y += v.y;
        }
        float ri = g_rin[node];
        float2 bb = ((const float2*)b2)[lane];
        acc.x = fmaxf(acc.x * ri + bb.x, 0.f);
        acc.y = fmaxf(acc.y * ri + bb.y, 0.f);
        gv = gid[node];
    }
    sv[wid][lane * 2]     = acc.x;
    sv[wid][lane * 2 + 1] = acc.y;
    if (lane == 0) sg[wid] = gv;
    __syncthreads();

    if (wid == 0) {
        int c0 = lane * 2;
        float a0 = 0.f, a1 = 0.f;
        int cnt = 0;
        int cur = sg[0];
        #pragma unroll
        for (int w = 0; w < 8; w++) {
            int gw = sg[w];
            if (gw != cur) {
                if (cur >= 0) {
                    atomicAdd(&g_gsum[cur * 64 + c0], a0);
                    atomicAdd(&g_gsum[cur * 64 + c0 + 1], a1);
                    if (lane == 0) atomicAdd(&g_gcnt[cur], cnt);
                }
                a0 = 0.f; a1 = 0.f; cnt = 0; cur = gw;
            }
            if (gw >= 0) { a0 += sv[w][c0]; a1 += sv[w][c0 + 1]; cnt++; }
        }
        if (cur >= 0) {
            atomicAdd(&g_gsum[cur * 64 + c0], a0);
            atomicAdd(&g_gsum[cur * 64 + c0 + 1], a1);
            if (lane == 0) atomicAdd(&g_gcnt[cur], cnt);
        }
    }
}

__global__ void classifier_kernel(const float* __restrict__ Wc1, const float* __restrict__ bc1,
                                  const float* __restrict__ Wc2, const float* __restrict__ bc2,
                                  const float* __restrict__ Wc3, const float* __restrict__ bc3,
                                  const float* __restrict__ Wc4, const float* __restrict__ bc4,
                                  float* __restrict__ out) {
    int g = blockIdx.x * blockDim.x + threadIdx.x;
    if (g >= NG) return;
    float inv = 1.f / fmaxf((float)g_gcnt[g], 1.f);
    float h[64];
    #pragma unroll
    for (int j = 0; j < 64; j++) h[j] = g_gsum[g * 64 + j] * inv;
    float t1[18];
    for (int j = 0; j < 18; j++) {
        float s = bc1[j];
        for (int k = 0; k < 64; k++) s += h[k] * Wc1[k * 18 + j];
        t1[j] = s;
    }
    float t2[12];
    for (int j = 0; j < 12; j++) {
        float s = bc2[j];
        for (int k = 0; k < 18; k++) s += t1[k] * Wc2[k * 12 + j];
        t2[j] = s;
    }
    float t3[6];
    for (int j = 0; j < 6; j++) {
        float s = bc3[j];
        for (int k = 0; k < 12; k++) s += t2[k] * Wc3[k * 6 + j];
        t3[j] = s;
    }
    for (int j = 0; j < 2; j++) {
        float s = bc4[j];
        for (int k = 0; k < 6; k++) s += t3[k] * Wc4[k * 2 + j];
        out[g * 2 + j] = s;
    }
}

// ---------------------------------------------------------------------------
extern "C" void kernel_launch(void* const* d_in, const int* in_sizes, int n_in,
                              void* d_out, int out_size) {
    const float* x   = (const float*)d_in[0];
    const int*   src = (const int*)d_in[1];
    const int*   dst = (const int*)d_in[2];
    const int*   gid = (const int*)d_in[3];
    const float* W1  = (const float*)d_in[4];
    const float* b1  = (const float*)d_in[5];
    const float* W2  = (const float*)d_in[6];
    const float* b2  = (const float*)d_in[7];
    const float* Wc1 = (const float*)d_in[8];
    const float* bc1 = (const float*)d_in[9];
    const float* Wc2 = (const float*)d_in[10];
    const float* bc2 = (const float*)d_in[11];
    const float* Wc3 = (const float*)d_in[12];
    const float* bc3 = (const float*)d_in[13];
    const float* Wc4 = (const float*)d_in[14];
    const float* bc4 = (const float*)d_in[15];
    float* out = (float*)d_out;

    float *p_rin, *p_rout;
    __half *p_agg1h, *p_h2in;
    cudaGetSymbolAddress((void**)&p_agg1h, g_agg1h);
    cudaGetSymbolAddress((void**)&p_h2in,  g_h2in);
    cudaGetSymbolAddress((void**)&p_rin,   g_rin);
    cudaGetSymbolAddress((void**)&p_rout,  g_rout);

    static int smem_set = 0;
    const int fused_smem = FUSED_SMEM_HALVES * 2;
    if (!smem_set) {
        cudaFuncSetAttribute(gemm_fused_kernel,
                             cudaFuncAttributeMaxDynamicSharedMemorySize, fused_smem);
        smem_set = 1;
    }

    zero_small_kernel<<<256, 256>>>();
    degree_kernel<<<(NE + 255) / 256, 256>>>(src, dst);
    finalize_deg_kernel<<<(NN + 255) / 256, 256>>>();

    // pre-scale + fp16 pack x
    xscale_kernel<<<(NN * 32 + 255) / 256, 256>>>(x);

    // CSR build (dst-major)
    scanA_kernel<<<NB, 1024>>>();
    scanB_kernel<<<1, 128>>>();
    scanC_kernel<<<NB, 1024>>>();
    scatter_kernel<<<(NE + 255) / 256, 256>>>(src, dst);

    // layer 1 gather (fp16 in/out, fp32 accumulate)
    agg1_kernel<<<(NN * 32 + 255) / 256, 256>>>();

    // fused fp16 tensor-core double GEMM
    gemm_fused_kernel<<<(NN + 63) / 64, 256, fused_smem>>>(
        p_agg1h, W1, W2, p_rin, b1, p_rout, p_h2in, NN);

    // layer 2 gather + pool (fp16 gather)
    agg2_pool_kernel<<<(NN + 7) / 8, 256>>>(gid, b2);

    classifier_kernel<<<(NG + 255) / 256, 256>>>(Wc1, bc1, Wc2, bc2, Wc3, bc3, Wc4, bc4, out);
}

// round 9
// speedup vs baseline: 2.3230x; 1.0069x over previous
#include <cuda_runtime.h>
#include <cuda_fp16.h>

#define NN 100000
#define NE 1600000
#define NG 512
#define NB 98   // ceil(NN/1024)

// ---- scratch (device globals; no allocation allowed) ----
__device__ int    g_degout[NN];
__device__ int    g_degin[NN];
__device__ float  g_rout[NN];
__device__ float  g_rin[NN];
__device__ int    g_rowptr[NN + 1];
__device__ int    g_cur[NN];
__device__ int    g_partial[NB];
__device__ int    g_base[NB];
__device__ int    g_csrc[NE];
__device__ __half g_xs[NN * 128];     // fp16(x * rout), 25.6 MB
__device__ __half g_h2in[NN * 64];    // 12.8 MB
__device__ float  g_gsum[NG * 64];
__device__ int    g_gcnt[NG];

// ---------------------------------------------------------------------------
__global__ void zero_small_kernel() {
    int i = blockIdx.x * blockDim.x + threadIdx.x;
    int stride = gridDim.x * blockDim.x;
    for (int j = i; j < NN; j += stride) { g_degout[j] = 0; g_degin[j] = 0; }
    for (int j = i; j < NG * 64; j += stride) g_gsum[j] = 0.f;
    for (int j = i; j < NG; j += stride) g_gcnt[j] = 0;
}

__global__ void degree_kernel(const int* __restrict__ src, const int* __restrict__ dst) {
    int e = blockIdx.x * blockDim.x + threadIdx.x;
    if (e < NE) {
        atomicAdd(&g_degout[src[e]], 1);
        atomicAdd(&g_degin[dst[e]], 1);
    }
}

__global__ void finalize_deg_kernel() {
    int i = blockIdx.x * blockDim.x + threadIdx.x;
    if (i < NN) {
        g_rout[i] = rsqrtf((float)max(g_degout[i], 1));
        g_rin[i]  = rsqrtf((float)max(g_degin[i], 1));
    }
}

// xs[n][d] = fp16( x[n][d] * rout[n] )
__global__ void xscale_kernel(const float* __restrict__ x) {
    int i = blockIdx.x * blockDim.x + threadIdx.x;   // float4 index
    int total = NN * 128 / 4;
    if (i >= total) return;
    int node = i >> 5;
    float r = g_rout[node];
    float4 v = ((const float4*)x)[i];
    __half2 h0 = __floats2half2_rn(v.x * r, v.y * r);
    __half2 h1 = __floats2half2_rn(v.z * r, v.w * r);
    ((uint2*)g_xs)[i] = make_uint2(*(unsigned*)&h0, *(unsigned*)&h1);
}

// ---- 3-phase exclusive scan of g_degin -> g_rowptr -------------------------
__global__ void scanA_kernel() {
    __shared__ int sh[1024];
    int idx = blockIdx.x * 1024 + threadIdx.x;
    sh[threadIdx.x] = (idx < NN) ? g_degin[idx] : 0;
    __syncthreads();
    for (int off = 512; off > 0; off >>= 1) {
        if (threadIdx.x < off) sh[threadIdx.x] += sh[threadIdx.x + off];
        __syncthreads();
    }
    if (threadIdx.x == 0) g_partial[blockIdx.x] = sh[0];
}

__global__ void scanB_kernel() {
    __shared__ int sh[128];
    int t = threadIdx.x;
    sh[t] = (t < NB) ? g_partial[t] : 0;
    __syncthreads();
    if (t == 0) {
        int run = 0;
        for (int b = 0; b < NB; b++) { int v = sh[b]; sh[b] = run; run += v; }
        g_rowptr[NN] = run;
    }
    __syncthreads();
    if (t < NB) g_base[t] = sh[t];
}

__global__ void scanC_kernel() {    // warp-shuffle scan
    __shared__ int warpsum[32];
    int tid = threadIdx.x;
    int idx = blockIdx.x * 1024 + tid;
    int lane = tid & 31, w = tid >> 5;
    int v = (idx < NN) ? g_degin[idx] : 0;
    int s = v;
    #pragma unroll
    for (int o = 1; o < 32; o <<= 1) {
        int t = __shfl_up_sync(0xffffffffu, s, o);
        if (lane >= o) s += t;
    }
    if (lane == 31) warpsum[w] = s;
    __syncthreads();
    if (w == 0) {
        int ws = warpsum[lane];
        #pragma unroll
        for (int o = 1; o < 32; o <<= 1) {
            int t = __shfl_up_sync(0xffffffffu, ws, o);
            if (lane >= o) ws += t;
        }
        warpsum[lane] = ws;
    }
    __syncthreads();
    int excl = s - v + (w > 0 ? warpsum[w - 1] : 0) + g_base[blockIdx.x];
    if (idx < NN) {
        g_rowptr[idx] = excl;
        g_cur[idx] = excl;
    }
}

__global__ void scatter_kernel(const int* __restrict__ src, const int* __restrict__ dst) {
    int e = blockIdx.x * blockDim.x + threadIdx.x;
    if (e < NE) {
        int pos = atomicAdd(&g_cur[dst[e]], 1);
        g_csrc[pos] = src[e];
    }
}

// ---- fused gather + FP16 double-GEMM ---------------------------------------
// As = segsum over in-edges of xs (gathered in-kernel, fp32 acc -> fp16 smem)
// h2in = fp16( rout ⊙ ( relu( rin ⊙ (As @ W1) + b1 ) @ W2 ) )
__device__ __forceinline__ unsigned smem_u32(const void* p) {
    return (unsigned)__cvta_generic_to_shared(p);
}
__device__ __forceinline__ void ldsm_x4(unsigned& r0, unsigned& r1, unsigned& r2, unsigned& r3,
                                        unsigned addr) {
    asm volatile("ldmatrix.sync.aligned.m8n8.x4.shared.b16 {%0,%1,%2,%3}, [%4];"
                 : "=r"(r0), "=r"(r1), "=r"(r2), "=r"(r3) : "r"(addr));
}
__device__ __forceinline__ void ldsm_x2t(unsigned& r0, unsigned& r1, unsigned addr) {
    asm volatile("ldmatrix.sync.aligned.m8n8.x2.trans.shared.b16 {%0,%1}, [%2];"
                 : "=r"(r0), "=r"(r1) : "r"(addr));
}
#define MMA_F16(c, a0, a1, a2, a3, b0, b1)                                    \
    asm volatile("mma.sync.aligned.m16n8k16.row.col.f32.f16.f16.f32 "         \
                 "{%0,%1,%2,%3}, {%4,%5,%6,%7}, {%8,%9}, {%0,%1,%2,%3};"      \
                 : "+f"(c[0]), "+f"(c[1]), "+f"(c[2]), "+f"(c[3])             \
                 : "r"(a0), "r"(a1), "r"(a2), "r"(a3), "r"(b0), "r"(b1))

#define AS_STRIDE 136
#define BS_STRIDE 72
#define OFF_AS  0
#define OFF_BS1 (64 * AS_STRIDE)
#define OFF_BS2 (OFF_BS1 + 128 * BS_STRIDE)
#define OFF_HS  (OFF_BS2 + 64 * BS_STRIDE)
#define FUSED_SMEM_HALVES (OFF_HS + 64 * BS_STRIDE)

__global__ void gemm_fused_kernel(const float* __restrict__ W1,  // [128,256]
                                  const float* __restrict__ W2,  // [256,64]
                                  const float* __restrict__ rin,
                                  const float* __restrict__ b1,
                                  const float* __restrict__ rout,
                                  __half* __restrict__ Cout,     // h2in [M,64]
                                  int M) {
    extern __shared__ __half sm[];
    __half* As  = sm + OFF_AS;
    __half* Bs1 = sm + OFF_BS1;
    __half* Bs2 = sm + OFF_BS2;
    __half* Hs  = sm + OFF_HS;

    int tid = threadIdx.x;
    int warp = tid >> 5, lane = tid & 31;
    int g = lane >> 2, q = lane & 3;
    int wm = warp & 1, wn = warp >> 1;
    int rowBase = blockIdx.x * 64;
    int l16 = lane & 15, lh = lane >> 4;

    float rs0[2], rs1[2], ro0[2], ro1[2];
    #pragma unroll
    for (int mt = 0; mt < 2; mt++) {
        int r = rowBase + wm * 32 + mt * 16 + g;
        rs0[mt] = (r < M) ? rin[r] : 0.f;
        ro0[mt] = (r < M) ? rout[r] : 0.f;
        rs1[mt] = (r + 8 < M) ? rin[r + 8] : 0.f;
        ro1[mt] = (r + 8 < M) ? rout[r + 8] : 0.f;
    }

    // phase 0: gather — warp w aggregates node rows 8w..8w+7 into As (fp16)
    #pragma unroll 1
    for (int rr = 0; rr < 8; rr++) {
        int row = warp * 8 + rr;
        int node = rowBase + row;
        float4 acc = make_float4(0.f, 0.f, 0.f, 0.f);
        if (node < M) {
            int beg = g_rowptr[node], end = g_rowptr[node + 1];
            int j = beg;
            for (; j + 3 < end; j += 4) {
                int s0 = g_csrc[j],     s1 = g_csrc[j + 1];
                int s2 = g_csrc[j + 2], s3 = g_csrc[j + 3];
                uint2 r0 = ((const uint2*)(g_xs + (size_t)s0 * 128))[lane];
                uint2 r1 = ((const uint2*)(g_xs + (size_t)s1 * 128))[lane];
                uint2 r2 = ((const uint2*)(g_xs + (size_t)s2 * 128))[lane];
                uint2 r3 = ((const uint2*)(g_xs + (size_t)s3 * 128))[lane];
                float2 a0 = __half22float2(*(__half2*)&r0.x), b0 = __half22float2(*(__half2*)&r0.y);
                float2 a1 = __half22float2(*(__half2*)&r1.x), b1v = __half22float2(*(__half2*)&r1.y);
                float2 a2 = __half22float2(*(__half2*)&r2.x), b2 = __half22float2(*(__half2*)&r2.y);
                float2 a3 = __half22float2(*(__half2*)&r3.x), b3 = __half22float2(*(__half2*)&r3.y);
                acc.x += a0.x + a1.x + a2.x + a3.x;
                acc.y += a0.y + a1.y + a2.y + a3.y;
                acc.z += b0.x + b1v.x + b2.x + b3.x;
                acc.w += b0.y + b1v.y + b2.y + b3.y;
            }
            for (; j < end; j++) {
                int s = g_csrc[j];
                uint2 r = ((const uint2*)(g_xs + (size_t)s * 128))[lane];
                float2 a = __half22float2(*(__half2*)&r.x), b = __half22float2(*(__half2*)&r.y);
                acc.x += a.x; acc.y += a.y; acc.z += b.x; acc.w += b.y;
            }
        }
        __half2 h0 = __floats2half2_rn(acc.x, acc.y);
        __half2 h1 = __floats2half2_rn(acc.z, acc.w);
        ((uint2*)(As + row * AS_STRIDE))[lane] = make_uint2(*(unsigned*)&h0, *(unsigned*)&h1);
    }

    float c2[2][2][4] = {};

    for (int qtr = 0; qtr < 4; qtr++) {
        // W1 tile: [128 k][64 n] fp32 -> fp16 Bs1
        #pragma unroll
        for (int it = 0; it < 8; it++) {
            int idx = tid + it * 256;
            int krow = idx >> 4;
            int c4 = (idx & 15) * 4;
            float4 v = *(const float4*)(W1 + (size_t)krow * 256 + qtr * 64 + c4);
            __half2 h0 = __floats2half2_rn(v.x, v.y);
            __half2 h1 = __floats2half2_rn(v.z, v.w);
            *(uint2*)(Bs1 + krow * BS_STRIDE + c4) = make_uint2(*(unsigned*)&h0, *(unsigned*)&h1);
        }
        __syncthreads();   // As (qtr 0) + Bs1 ready

        // MMA1: c1 = A_tile @ W1_quarter  (64x64, K=128)
        float c1[2][2][4] = {};
        #pragma unroll
        for (int ks = 0; ks < 8; ks++) {
            unsigned a[2][4], b[2][2];
            #pragma unroll
            for (int mt = 0; mt < 2; mt++)
                ldsm_x4(a[mt][0], a[mt][1], a[mt][2], a[mt][3],
                        smem_u32(As + (wm * 32 + mt * 16 + l16) * AS_STRIDE + ks * 16 + lh * 8));
            #pragma unroll
            for (int nt = 0; nt < 2; nt++)
                ldsm_x2t(b[nt][0], b[nt][1],
                         smem_u32(Bs1 + (ks * 16 + l16) * BS_STRIDE + wn * 16 + nt * 8));
            #pragma unroll
            for (int mt = 0; mt < 2; mt++)
                #pragma unroll
                for (int nt = 0; nt < 2; nt++)
                    MMA_F16(c1[mt][nt], a[mt][0], a[mt][1], a[mt][2], a[mt][3],
                            b[nt][0], b[nt][1]);
        }

        // epilogue1: relu(rin*c1 + b1) -> Hs fp16 [64 row][64 col]
        #pragma unroll
        for (int nt = 0; nt < 2; nt++) {
            int cL0 = wn * 16 + nt * 8 + 2 * q;
            float2 bb = *(const float2*)(b1 + qtr * 64 + cL0);
            #pragma unroll
            for (int mt = 0; mt < 2; mt++) {
                int r0 = wm * 32 + mt * 16 + g;
                __half2 h0 = __floats2half2_rn(fmaxf(c1[mt][nt][0] * rs0[mt] + bb.x, 0.f),
                                               fmaxf(c1[mt][nt][1] * rs0[mt] + bb.y, 0.f));
                __half2 h1 = __floats2half2_rn(fmaxf(c1[mt][nt][2] * rs1[mt] + bb.x, 0.f),
                                               fmaxf(c1[mt][nt][3] * rs1[mt] + bb.y, 0.f));
                *(__half2*)(Hs + r0 * BS_STRIDE + cL0) = h0;
                *(__half2*)(Hs + (r0 + 8) * BS_STRIDE + cL0) = h1;
            }
        }

        // W2 tile: rows qtr*64..+64 [64 k][64 n] -> fp16 Bs2
        #pragma unroll
        for (int it = 0; it < 4; it++) {
            int idx = tid + it * 256;
            int krow = idx >> 4;
            int c4 = (idx & 15) * 4;
            float4 v = *(const float4*)(W2 + (size_t)(qtr * 64 + krow) * 64 + c4);
            __half2 h0 = __floats2half2_rn(v.x, v.y);
            __half2 h1 = __floats2half2_rn(v.z, v.w);
            *(uint2*)(Bs2 + krow * BS_STRIDE + c4) = make_uint2(*(unsigned*)&h0, *(unsigned*)&h1);
        }
        __syncthreads();   // Hs + Bs2 ready

        // MMA2: c2 += h1_quarter @ W2_quarter  (64x64, K=64)
        #pragma unroll
        for (int ks = 0; ks < 4; ks++) {
            unsigned a[2][4], b[2][2];
            #pragma unroll
            for (int mt = 0; mt < 2; mt++)
                ldsm_x4(a[mt][0], a[mt][1], a[mt][2], a[mt][3],
                        smem_u32(Hs + (wm * 32 + mt * 16 + l16) * BS_STRIDE + ks * 16 + lh * 8));
            #pragma unroll
            for (int nt = 0; nt < 2; nt++)
                ldsm_x2t(b[nt][0], b[nt][1],
                         smem_u32(Bs2 + (ks * 16 + l16) * BS_STRIDE + wn * 16 + nt * 8));
            #pragma unroll
            for (int mt = 0; mt < 2; mt++)
                #pragma unroll
                for (int nt = 0; nt < 2; nt++)
                    MMA_F16(c2[mt][nt], a[mt][0], a[mt][1], a[mt][2], a[mt][3],
                            b[nt][0], b[nt][1]);
        }
        __syncthreads();   // all MMA2 reads done before next quarter's writes
    }

    // final epilogue: h2in = fp16(rout * c2)
    #pragma unroll
    for (int mt = 0; mt < 2; mt++) {
        int r0 = rowBase + wm * 32 + mt * 16 + g;
        #pragma unroll
        for (int nt = 0; nt < 2; nt++) {
            int c0 = wn * 16 + nt * 8 + 2 * q;
            if (r0 < M)
                *(__half2*)(Cout + (size_t)r0 * 64 + c0) =
                    __floats2half2_rn(c2[mt][nt][0] * ro0[mt], c2[mt][nt][1] * ro0[mt]);
            if (r0 + 8 < M)
                *(__half2*)(Cout + (size_t)(r0 + 8) * 64 + c0) =
                    __floats2half2_rn(c2[mt][nt][2] * ro1[mt], c2[mt][nt][3] * ro1[mt]);
        }
    }
}

// ---- layer-2 aggregation fused with mean-pool reduction (fp16 gather) ------
__global__ void agg2_pool_kernel(const int* __restrict__ gid, const float* __restrict__ b2) {
    __shared__ float sv[8][64];
    __shared__ int sg[8];
    int wid = threadIdx.x >> 5, lane = threadIdx.x & 31;
    int node = blockIdx.x * 8 + wid;
    float2 acc = make_float2(0.f, 0.f);
    int gv = -1;
    if (node < NN) {
        int beg = g_rowptr[node], end = g_rowptr[node + 1];
        int j = beg;
        for (; j + 3 < end; j += 4) {
            int s0 = g_csrc[j],     s1 = g_csrc[j + 1];
            int s2 = g_csrc[j + 2], s3 = g_csrc[j + 3];
            float2 v0 = __half22float2(((const __half2*)(g_h2in + (size_t)s0 * 64))[lane]);
            float2 v1 = __half22float2(((const __half2*)(g_h2in + (size_t)s1 * 64))[lane]);
            float2 v2 = __half22float2(((const __half2*)(g_h2in + (size_t)s2 * 64))[lane]);
            float2 v3 = __half22float2(((const __half2*)(g_h2in + (size_t)s3 * 64))[lane]);
            acc.x += v0.x + v1.x + v2.x + v3.x;
            acc.y += v0.y + v1.y + v2.y + v3.y;
        }
        for (; j < end; j++) {
            int s = g_csrc[j];
            float2 v = __half22float2(((const __half2*)(g_h2in + (size_t)s * 64))[lane]);
            acc.x += v.x; acc.y += v.y;
        }
        float ri = g_rin[node];
        float2 bb = ((const float2*)b2)[lane];
        acc.x = fmaxf(acc.x * ri + bb.x, 0.f);
        acc.y = fmaxf(acc.y * ri + bb.y, 0.f);
        gv = gid[node];
    }
    sv[wid][lane * 2]     = acc.x;
    sv[wid][lane * 2 + 1] = acc.y;
    if (lane == 0) sg[wid] = gv;
    __syncthreads();

    if (wid == 0) {
        int c0 = lane * 2;
        float a0 = 0.f, a1 = 0.f;
        int cnt = 0;
        int cur = sg[0];
        #pragma unroll
        for (int w = 0; w < 8; w++) {
            int gw = sg[w];
            if (gw != cur) {
                if (cur >= 0) {
                    atomicAdd(&g_gsum[cur * 64 + c0], a0);
                    atomicAdd(&g_gsum[cur * 64 + c0 + 1], a1);
                    if (lane == 0) atomicAdd(&g_gcnt[cur], cnt);
                }
                a0 = 0.f; a1 = 0.f; cnt = 0; cur = gw;
            }
            if (gw >= 0) { a0 += sv[w][c0]; a1 += sv[w][c0 + 1]; cnt++; }
        }
        if (cur >= 0) {
            atomicAdd(&g_gsum[cur * 64 + c0], a0);
            atomicAdd(&g_gsum[cur * 64 + c0 + 1], a1);
            if (lane == 0) atomicAdd(&g_gcnt[cur], cnt);
        }
    }
}

__global__ void classifier_kernel(const float* __restrict__ Wc1, const float* __restrict__ bc1,
                                  const float* __restrict__ Wc2, const float* __restrict__ bc2,
                                  const float* __restrict__ Wc3, const float* __restrict__ bc3,
                                  const float* __restrict__ Wc4, const float* __restrict__ bc4,
                                  float* __restrict__ out) {
    int g = blockIdx.x * blockDim.x + threadIdx.x;
    if (g >= NG) return;
    float inv = 1.f / fmaxf((float)g_gcnt[g], 1.f);
    float h[64];
    #pragma unroll
    for (int j = 0; j < 64; j++) h[j] = g_gsum[g * 64 + j] * inv;
    float t1[18];
    for (int j = 0; j < 18; j++) {
        float s = bc1[j];
        for (int k = 0; k < 64; k++) s += h[k] * Wc1[k * 18 + j];
        t1[j] = s;
    }
    float t2[12];
    for (int j = 0; j < 12; j++) {
        float s = bc2[j];
        for (int k = 0; k < 18; k++) s += t1[k] * Wc2[k * 12 + j];
        t2[j] = s;
    }
    float t3[6];
    for (int j = 0; j < 6; j++) {
        float s = bc3[j];
        for (int k = 0; k < 12; k++) s += t2[k] * Wc3[k * 6 + j];
        t3[j] = s;
    }
    for (int j = 0; j < 2; j++) {
        float s = bc4[j];
        for (int k = 0; k < 6; k++) s += t3[k] * Wc4[k * 2 + j];
        out[g * 2 + j] = s;
    }
}

// ---------------------------------------------------------------------------
extern "C" void kernel_launch(void* const* d_in, const int* in_sizes, int n_in,
                              void* d_out, int out_size) {
    const float* x   = (const float*)d_in[0];
    const int*   src = (const int*)d_in[1];
    const int*   dst = (const int*)d_in[2];
    const int*   gid = (const int*)d_in[3];
    const float* W1  = (const float*)d_in[4];
    const float* b1  = (const float*)d_in[5];
    const float* W2  = (const float*)d_in[6];
    const float* b2  = (const float*)d_in[7];
    const float* Wc1 = (const float*)d_in[8];
    const float* bc1 = (const float*)d_in[9];
    const float* Wc2 = (const float*)d_in[10];
    const float* bc2 = (const float*)d_in[11];
    const float* Wc3 = (const float*)d_in[12];
    const float* bc3 = (const float*)d_in[13];
    const float* Wc4 = (const float*)d_in[14];
    const float* bc4 = (const float*)d_in[15];
    float* out = (float*)d_out;

    float *p_rin, *p_rout;
    __half* p_h2in;
    cudaGetSymbolAddress((void**)&p_h2in, g_h2in);
    cudaGetSymbolAddress((void**)&p_rin,  g_rin);
    cudaGetSymbolAddress((void**)&p_rout, g_rout);

    static int smem_set = 0;
    const int fused_smem = FUSED_SMEM_HALVES * 2;
    if (!smem_set) {
        cudaFuncSetAttribute(gemm_fused_kernel,
                             cudaFuncAttributeMaxDynamicSharedMemorySize, fused_smem);
        smem_set = 1;
    }

    zero_small_kernel<<<256, 256>>>();
    degree_kernel<<<(NE + 255) / 256, 256>>>(src, dst);
    finalize_deg_kernel<<<(NN + 255) / 256, 256>>>();

    // pre-scale + fp16 pack x
    xscale_kernel<<<(NN * 32 + 255) / 256, 256>>>(x);

    // CSR build (dst-major)
    scanA_kernel<<<NB, 1024>>>();
    scanB_kernel<<<1, 128>>>();
    scanC_kernel<<<NB, 1024>>>();
    scatter_kernel<<<(NE + 255) / 256, 256>>>(src, dst);

    // fused gather + fp16 tensor-core double GEMM
    gemm_fused_kernel<<<(NN + 63) / 64, 256, fused_smem>>>(
        W1, W2, p_rin, b1, p_rout, p_h2in, NN);

    // layer 2 gather + pool (fp16 gather)
    agg2_pool_kernel<<<(NN + 7) / 8, 256>>>(gid, b2);

    classifier_kernel<<<(NG + 255) / 256, 256>>>(Wc1, bc1, Wc2, bc2, Wc3, bc3, Wc4, bc4, out);
}